// round 3
// baseline (speedup 1.0000x reference)
#include <cuda_runtime.h>

// ---------------------------------------------------------------------------
// Problem constants
// ---------------------------------------------------------------------------
#define B_   8
#define S_   32
#define N_   2000
#define GH_  32
#define H_   64
#define D_   (N_ * GH_)     // 64000  LSTM input size
#define BS_  (B_ * S_)      // 256    batch*seq rows
#define G4_  (4 * H_)       // 256    gate count

// Scratch (no cudaMalloc allowed -> __device__ globals)
__device__ float g_lstm_in[(size_t)BS_ * D_];   // 65.5 MB  [bs][d]
__device__ float g_pg[BS_ * G4_];               // 256 KB   pre-gates [bs][k]

// Packed fp32x2 FMA (B300: 2x FFMA throughput, only reachable via PTX)
#define FMA2(d, a, b, c) \
    asm("fma.rn.f32x2 %0, %1, %2, %3;" : "=l"(d) : "l"(a), "l"(b), "l"(c))

// Monotonic float<->uint key for shared atomicMax over floats
__device__ __forceinline__ unsigned fkey(float f) {
    unsigned u = __float_as_uint(f);
    return (u & 0x80000000u) ? ~u : (u | 0x80000000u);
}
__device__ __forceinline__ float funkey(unsigned u) {
    return __uint_as_float((u & 0x80000000u) ? (u ^ 0x80000000u) : ~u);
}

// ---------------------------------------------------------------------------
// Kernel 0: zero the pre-gate accumulator (GEMM uses atomicAdd K-split merge)
// ---------------------------------------------------------------------------
__global__ void zero_pg_k() {
    int i = blockIdx.x * blockDim.x + threadIdx.x;   // grid covers 256*256
    g_pg[i] = 0.0f;
}

// ---------------------------------------------------------------------------
// Kernel 1: GAT per (b,s) slice + fused lstm_in construction
//   One CTA per bs row. x slice (8KB) + seg arrays in shared.
//   Pass 1: segment max over dst. Pass 2: exp-sum + weighted sum.
//   Epilogue: lstm_in[bs, n*32+g] = relu(agg[n]*w_lin[g] + gat_bias[g])
// ---------------------------------------------------------------------------
__global__ __launch_bounds__(256) void gat_k(
    const float* __restrict__ x,         // [BS][N]
    const int*   __restrict__ ei,        // [2][E]
    const float* __restrict__ w_lin,     // [GH]
    const float* __restrict__ att_src,   // [GH]
    const float* __restrict__ att_dst,   // [GH]
    const float* __restrict__ gbias,     // [GH]
    int E)
{
    __shared__ float    xs[N_];
    __shared__ unsigned mx[N_];
    __shared__ float    den[N_];
    __shared__ float    num[N_];

    const int bs  = blockIdx.x;
    const int tid = threadIdx.x;
    const float* xr = x + (size_t)bs * N_;

    for (int n = tid; n < N_; n += 256) {
        xs[n]  = xr[n];
        mx[n]  = 0u;           // below every finite key
        den[n] = 0.0f;
        num[n] = 0.0f;
    }
    // scalar attention coefficients: cs = w_lin . att_src, cd = w_lin . att_dst
    float cs = 0.0f, cd = 0.0f;
    for (int g = 0; g < GH_; g++) {
        float w = w_lin[g];
        cs = fmaf(w, att_src[g], cs);
        cd = fmaf(w, att_dst[g], cd);
    }
    __syncthreads();

    const int Et = E + N_;   // with self loops appended

    // Pass 1: segment max
    for (int t = tid; t < Et; t += 256) {
        int s, d;
        if (t < E) { s = ei[t]; d = ei[E + t]; } else { s = t - E; d = s; }
        float z = cs * xs[s] + cd * xs[d];
        float e = (z > 0.0f) ? z : 0.2f * z;       // leaky_relu(0.2)
        atomicMax(&mx[d], fkey(e));
    }
    __syncthreads();

    // Pass 2: exp-sum + weighted numerator
    for (int t = tid; t < Et; t += 256) {
        int s, d;
        if (t < E) { s = ei[t]; d = ei[E + t]; } else { s = t - E; d = s; }
        float z = cs * xs[s] + cd * xs[d];
        float e = (z > 0.0f) ? z : 0.2f * z;
        float m = funkey(mx[d]);
        float w = __expf(e - m);
        atomicAdd(&den[d], w);
        atomicAdd(&num[d], w * xs[s]);
    }
    __syncthreads();

    for (int n = tid; n < N_; n += 256) num[n] = num[n] / den[n];  // agg
    __syncthreads();

    // Epilogue: write lstm_in row (float4 vectorized, 16000 float4 per row)
    float* outr = g_lstm_in + (size_t)bs * D_;
    const float4* w4 = (const float4*)w_lin;
    const float4* b4 = (const float4*)gbias;
    for (int i = tid; i < N_ * (GH_ / 4); i += 256) {
        int n = i >> 3;          // GH_/4 = 8 float4 per node
        int q = i & 7;
        float  a = num[n];
        float4 w = w4[q];
        float4 bb = b4[q];
        float4 o;
        o.x = fmaxf(fmaf(a, w.x, bb.x), 0.0f);
        o.y = fmaxf(fmaf(a, w.y, bb.y), 0.0f);
        o.z = fmaxf(fmaf(a, w.z, bb.z), 0.0f);
        o.w = fmaxf(fmaf(a, w.w, bb.w), 0.0f);
        ((float4*)outr)[i] = o;
    }
}

// ---------------------------------------------------------------------------
// Kernel 2: input-projection GEMM  g_pg[bs][k] += sum_d lstm_in[bs][d]*W_ih[k][d]
//   M=N=256, K=64000. K-split over blockIdx.z, atomicAdd merge.
//   Inner loop uses packed fma.rn.f32x2 (2 MACs/instr).
// ---------------------------------------------------------------------------
#define TBS    64            // bs tile
#define TKG    64            // gate tile
#define KC     32            // K chunk staged in shared
#define LDT    36            // padded row stride (keeps 16B alignment)
#define KSPLIT 50
#define KPER   (D_ / KSPLIT) // 1280, 40 chunks of 32

__global__ __launch_bounds__(256) void gemm_k(const float* __restrict__ W_ih)
{
    __shared__ float As[TBS * LDT];
    __shared__ float Ws[TKG * LDT];

    const int t   = threadIdx.x;
    const int bs0 = blockIdx.x * TBS;
    const int k0  = blockIdx.y * TKG;
    const int d0  = blockIdx.z * KPER;
    const int rm  = t & 15;      // bs micro index (stride-16 x4)
    const int cn  = t >> 4;      // k  micro index (stride-16 x4)

    unsigned long long acc[4][4];
#pragma unroll
    for (int i = 0; i < 4; i++)
#pragma unroll
        for (int j = 0; j < 4; j++) acc[i][j] = 0ull;

    const float* Xp = g_lstm_in + (size_t)bs0 * D_ + d0;
    const float* Wp = W_ih      + (size_t)k0  * D_ + d0;

    for (int dc = 0; dc < KPER; dc += KC) {
#pragma unroll
        for (int i = 0; i < 2; i++) {             // 512 float4 slots, A tile
            int s = t + i * 256;
            int r = s >> 3, c = s & 7;
            *(float4*)(&As[r * LDT + c * 4]) =
                *(const float4*)(Xp + (size_t)r * D_ + dc + c * 4);
        }
#pragma unroll
        for (int i = 0; i < 2; i++) {             // W tile
            int s = t + i * 256;
            int r = s >> 3, c = s & 7;
            *(float4*)(&Ws[r * LDT + c * 4]) =
                *(const float4*)(Wp + (size_t)r * D_ + dc + c * 4);
        }
        __syncthreads();

#pragma unroll
        for (int kk = 0; kk < KC; kk += 2) {
            unsigned long long a2[4], b2[4];
#pragma unroll
            for (int i = 0; i < 4; i++)
                a2[i] = *(const unsigned long long*)(&As[(rm + 16 * i) * LDT + kk]);
#pragma unroll
            for (int j = 0; j < 4; j++)
                b2[j] = *(const unsigned long long*)(&Ws[(cn + 16 * j) * LDT + kk]);
#pragma unroll
            for (int i = 0; i < 4; i++)
#pragma unroll
                for (int j = 0; j < 4; j++)
                    FMA2(acc[i][j], a2[i], b2[j], acc[i][j]);
        }
        __syncthreads();
    }

#pragma unroll
    for (int i = 0; i < 4; i++)
#pragma unroll
        for (int j = 0; j < 4; j++) {
            float2 v = *reinterpret_cast<float2*>(&acc[i][j]);
            atomicAdd(&g_pg[(bs0 + rm + 16 * i) * G4_ + (k0 + cn + 16 * j)],
                      v.x + v.y);
        }
}

// ---------------------------------------------------------------------------
// Kernel 3: LSTM recurrence (per-batch independent, 8 CTAs) + fused head GEMV
// ---------------------------------------------------------------------------
__global__ __launch_bounds__(256) void lstm_k(
    const float* __restrict__ W_hh,     // [256][64]
    const float* __restrict__ b_ih,     // [256]
    const float* __restrict__ b_hh,     // [256]
    const float* __restrict__ W_head,   // [N][64]
    const float* __restrict__ b_head,   // [N]
    float*       __restrict__ outp)     // [B][N]
{
    __shared__ float hs[H_];
    __shared__ float cv[H_];
    __shared__ float gsh[G4_];

    const int b = blockIdx.x;
    const int t = threadIdx.x;      // 256 threads = one thread per gate k

    if (t < H_) { hs[t] = 0.0f; cv[t] = 0.0f; }
    const float bsum = b_ih[t] + b_hh[t];
    const float* wr  = W_hh + t * H_;
    __syncthreads();

    for (int s = 0; s < S_; s++) {
        float a0 = 0.f, a1 = 0.f, a2 = 0.f, a3 = 0.f;
#pragma unroll
        for (int h = 0; h < H_; h += 4) {
            a0 = fmaf(wr[h],     hs[h],     a0);
            a1 = fmaf(wr[h + 1], hs[h + 1], a1);
            a2 = fmaf(wr[h + 2], hs[h + 2], a2);
            a3 = fmaf(wr[h + 3], hs[h + 3], a3);
        }
        gsh[t] = g_pg[(b * S_ + s) * G4_ + t] + bsum + ((a0 + a1) + (a2 + a3));
        __syncthreads();
        if (t < H_) {
            float ig = gsh[t];
            float fg = gsh[H_ + t];
            float gg = gsh[2 * H_ + t];
            float og = gsh[3 * H_ + t];
            float si = 1.0f / (1.0f + expf(-ig));
            float sf = 1.0f / (1.0f + expf(-fg));
            float so = 1.0f / (1.0f + expf(-og));
            float c  = sf * cv[t] + si * tanhf(gg);
            cv[t] = c;
            hs[t] = so * tanhf(c);
        }
        __syncthreads();
    }

    // head: out[b][n] = hT . W_head[n] + b_head[n]
    for (int n = t; n < N_; n += 256) {
        float acc = b_head[n];
        const float* whr = W_head + n * H_;
#pragma unroll 8
        for (int h = 0; h < H_; h++) acc = fmaf(whr[h], hs[h], acc);
        outp[b * N_ + n] = acc;
    }
}

// ---------------------------------------------------------------------------
// Launch
// ---------------------------------------------------------------------------
extern "C" void kernel_launch(void* const* d_in, const int* in_sizes, int n_in,
                              void* d_out, int out_size)
{
    const float* x        = (const float*)d_in[0];
    const int*   ei       = (const int*)  d_in[1];
    const float* w_lin    = (const float*)d_in[2];
    const float* att_src  = (const float*)d_in[3];
    const float* att_dst  = (const float*)d_in[4];
    const float* gbias    = (const float*)d_in[5];
    const float* W_ih     = (const float*)d_in[6];
    const float* W_hh     = (const float*)d_in[7];
    const float* b_ih     = (const float*)d_in[8];
    const float* b_hh     = (const float*)d_in[9];
    const float* W_head   = (const float*)d_in[10];
    const float* b_head   = (const float*)d_in[11];
    float*       out      = (float*)d_out;
    const int    E        = in_sizes[1] / 2;

    zero_pg_k<<<(BS_ * G4_) / 256, 256>>>();
    gat_k<<<BS_, 256>>>(x, ei, w_lin, att_src, att_dst, gbias, E);
    gemm_k<<<dim3(BS_ / TBS, G4_ / TKG, KSPLIT), 256>>>(W_ih);
    lstm_k<<<B_, 256>>>(W_hh, b_ih, b_hh, W_head, b_head, out);
}

// round 11
// speedup vs baseline: 1.8550x; 1.8550x over previous
#include <cuda_runtime.h>
#include <cuda_bf16.h>
#include <cstdint>

// ---------------------------------------------------------------------------
#define B_   8
#define S_   32
#define N_   2000
#define GH_  32
#define H_   64
#define D_   64000          // N_*GH_
#define BS_  256
#define G4_  256

#define KSPLIT 74           // K-splits (chunks of 64 over D_)
#define NSPL   2            // gate halves (128 each)
#define NCHUNK 1000         // D_/64
#define NST    28           // staged agg nodes per CTA (2 per chunk, max 14 chunks)

__device__ float g_agg[BS_ * N_];                    // 2 MB
__device__ float g_pg[BS_ * G4_];                    // 256 KB pre-gates
__device__ float g_part[KSPLIT * BS_ * G4_];         // 19.4 MB GEMM partials

// ---------------------------------------------------------------------------
// helpers
// ---------------------------------------------------------------------------
__device__ __forceinline__ uint32_t smem_u32(const void* p) {
    uint32_t a;
    asm("{ .reg .u64 t; cvta.to.shared.u64 t, %1; cvt.u32.u64 %0, t; }"
        : "=r"(a) : "l"(p));
    return a;
}
// SW128-style swizzle (permutes 16B chunks within a 128B row by row%8)
#define SWZ(o) ((o) ^ (((o) >> 3) & 0x70))

__device__ __forceinline__ void ldsm4(uint32_t* r, uint32_t addr) {
    asm volatile("ldmatrix.sync.aligned.m8n8.x4.shared.b16 {%0,%1,%2,%3}, [%4];"
                 : "=r"(r[0]), "=r"(r[1]), "=r"(r[2]), "=r"(r[3]) : "r"(addr));
}
__device__ __forceinline__ void mma16816(float* c, const uint32_t* a,
                                         const uint32_t* b) {
    asm volatile(
        "mma.sync.aligned.m16n8k16.row.col.f32.bf16.bf16.f32 "
        "{%0,%1,%2,%3}, {%4,%5,%6,%7}, {%8,%9}, {%0,%1,%2,%3};"
        : "+f"(c[0]), "+f"(c[1]), "+f"(c[2]), "+f"(c[3])
        : "r"(a[0]), "r"(a[1]), "r"(a[2]), "r"(a[3]), "r"(b[0]), "r"(b[1]));
}

// ---------------------------------------------------------------------------
// Kernel 1: GAT — single edge pass, 2 bs-rows per CTA. Writes agg only.
// ---------------------------------------------------------------------------
__global__ __launch_bounds__(256) void gat_k(
    const float* __restrict__ x, const int* __restrict__ ei,
    const float* __restrict__ w_lin, const float* __restrict__ att_src,
    const float* __restrict__ att_dst, int E)
{
    __shared__ float xs[2][N_];
    __shared__ float den[2][N_];
    __shared__ float num[2][N_];

    const int bs0 = blockIdx.x * 2;
    const int tid = threadIdx.x;

    for (int n = tid; n < N_; n += 256) {
        xs[0][n] = x[(size_t)bs0 * N_ + n];
        xs[1][n] = x[(size_t)(bs0 + 1) * N_ + n];
        den[0][n] = 0.f; den[1][n] = 0.f;
        num[0][n] = 0.f; num[1][n] = 0.f;
    }
    float cs = 0.f, cd = 0.f;
    for (int g = 0; g < GH_; g++) {
        float w = w_lin[g];
        cs = fmaf(w, att_src[g], cs);
        cd = fmaf(w, att_dst[g], cd);
    }
    __syncthreads();

    const int Et = E + N_;
    for (int t = tid; t < Et; t += 256) {
        int s, d;
        if (t < E) { s = ei[t]; d = ei[E + t]; } else { s = t - E; d = s; }
        float x0s = xs[0][s], x0d = xs[0][d];
        float x1s = xs[1][s], x1d = xs[1][d];
        float z0 = cs * x0s + cd * x0d;
        float z1 = cs * x1s + cd * x1d;
        float e0 = (z0 > 0.f) ? z0 : 0.2f * z0;
        float e1 = (z1 > 0.f) ? z1 : 0.2f * z1;
        float w0 = __expf(e0);
        float w1 = __expf(e1);
        atomicAdd(&den[0][d], w0);
        atomicAdd(&num[0][d], w0 * x0s);
        atomicAdd(&den[1][d], w1);
        atomicAdd(&num[1][d], w1 * x1s);
    }
    __syncthreads();

    for (int n = tid; n < N_; n += 256) {
        g_agg[(size_t)bs0 * N_ + n]       = num[0][n] / den[0][n];
        g_agg[(size_t)(bs0 + 1) * N_ + n] = num[1][n] / den[1][n];
    }
}

// ---------------------------------------------------------------------------
// Kernel 2: bf16 hi/lo GEMM via mma.sync (HMMA). pg = A[256,64000]*W^T.
//   grid (74 K-splits, 2 gate-halves). CTA tile 256x128, warp tile 64x64.
//   A generated on the fly from agg; partials to g_part (no atomics).
// ---------------------------------------------------------------------------
#define OFF_WL   0
#define OFF_GB   128
#define OFF_AGG  256                       // 256*28*4 = 28672
#define OFF_AHI  29056                     // 256x64 bf16 = 32768
#define OFF_ALO  61824
#define OFF_BHI  94592                     // 128x64 bf16 = 16384
#define OFF_BLO  110976
#define SMEM_TOT 127360

__global__ __launch_bounds__(256) void gemm_k(
    const float* __restrict__ W_ih,
    const float* __restrict__ w_lin_g, const float* __restrict__ gbias_g)
{
    extern __shared__ __align__(128) char sm[];
    const uint32_t sb = smem_u32(sm);
    const int tid  = threadIdx.x;
    const int lane = tid & 31;
    const int wid  = tid >> 5;
    const int z    = blockIdx.x;           // K split
    const int nh   = blockIdx.y;           // gate half
    const int c0   = z * NCHUNK / KSPLIT;
    const int c1   = (z + 1) * NCHUNK / KSPLIT;
    const int n0   = c0 * 2;

    if (tid < 32) {
        ((float*)(sm + OFF_WL))[tid] = w_lin_g[tid];
        ((float*)(sm + OFF_GB))[tid] = gbias_g[tid];
    }
    for (int i = tid; i < 256 * NST; i += 256) {
        int row = i / NST, nl = i % NST;
        ((float*)(sm + OFF_AGG))[i] = g_agg[(size_t)row * N_ + n0 + nl];
    }
    __syncthreads();

    const float* wl = (const float*)(sm + OFF_WL);
    const float* gb = (const float*)(sm + OFF_GB);
    const float* ag = (const float*)(sm + OFF_AGG);

    // warp tile: 64x64; CTA = 4x2 warp grid over 256x128
    const int mw = (wid & 3) * 64;
    const int nw = (wid >> 2) * 64;

    // per-lane ldmatrix row components
    const uint32_t rowA = (uint32_t)(mw + (lane & 15)) * 128u;
    const uint32_t khA  = (uint32_t)(lane >> 4);
    const uint32_t swA  = (uint32_t)(lane & 7);
    const uint32_t rowB = (uint32_t)(nw + (lane & 7) + ((lane >> 4) << 3)) * 128u;
    const uint32_t khB  = (uint32_t)((lane >> 3) & 1);
    const uint32_t swB  = (uint32_t)(lane & 7);

    float acc[4][8][4];
#pragma unroll
    for (int mt = 0; mt < 4; mt++)
#pragma unroll
        for (int nt = 0; nt < 8; nt++)
#pragma unroll
            for (int q = 0; q < 4; q++) acc[mt][nt][q] = 0.f;

    for (int c = c0; c < c1; c++) {
        // ---- generate A tile (256x64 bf16 hi/lo) from agg ----
        const int cl2 = (c - c0) * 2;
#pragma unroll
        for (int i = 0; i < 16; i++) {
            int idx = tid + i * 256;
            int row = idx >> 4, c4 = idx & 15;
            float a  = ag[row * NST + cl2 + (c4 >> 3)];
            int   g0 = (c4 & 7) * 4;
            __nv_bfloat16 hi[4], lo[4];
#pragma unroll
            for (int j = 0; j < 4; j++) {
                float v = fmaxf(fmaf(a, wl[g0 + j], gb[g0 + j]), 0.f);
                hi[j] = __float2bfloat16_rn(v);
                lo[j] = __float2bfloat16_rn(v - __bfloat162float(hi[j]));
            }
            uint32_t off = SWZ((uint32_t)(row * 128 + c4 * 8));
            *(uint2*)(sm + OFF_AHI + off) = *(uint2*)hi;
            *(uint2*)(sm + OFF_ALO + off) = *(uint2*)lo;
        }
        // ---- load + convert W tile (128x64) ----
#pragma unroll
        for (int i = 0; i < 8; i++) {
            int idx = tid + i * 256;
            int row = idx >> 4, c4 = idx & 15;
            float4 w = *(const float4*)(W_ih + (size_t)(nh * 128 + row) * D_ +
                                        c * 64 + c4 * 4);
            float v[4] = {w.x, w.y, w.z, w.w};
            __nv_bfloat16 hi[4], lo[4];
#pragma unroll
            for (int j = 0; j < 4; j++) {
                hi[j] = __float2bfloat16_rn(v[j]);
                lo[j] = __float2bfloat16_rn(v[j] - __bfloat162float(hi[j]));
            }
            uint32_t off = SWZ((uint32_t)(row * 128 + c4 * 8));
            *(uint2*)(sm + OFF_BHI + off) = *(uint2*)hi;
            *(uint2*)(sm + OFF_BLO + off) = *(uint2*)lo;
        }
        __syncthreads();

        // ---- mma over 4 k16 steps, 3 hi/lo terms ----
#pragma unroll
        for (int ks = 0; ks < 4; ks++) {
            uint32_t af[4][4], bh[4][4], bl2[4][4];
            const uint32_t cA = (((uint32_t)(ks * 2) + khA) ^ swA) << 4;
            const uint32_t cB = (((uint32_t)(ks * 2) + khB) ^ swB) << 4;
#pragma unroll
            for (int mt = 0; mt < 4; mt++)
                ldsm4(af[mt], sb + OFF_AHI + rowA + mt * 2048 + cA);
#pragma unroll
            for (int np = 0; np < 4; np++)
                ldsm4(bh[np], sb + OFF_BHI + rowB + np * 2048 + cB);
#pragma unroll
            for (int mt = 0; mt < 4; mt++)
#pragma unroll
                for (int nt = 0; nt < 8; nt++)
                    mma16816(acc[mt][nt], af[mt], &bh[nt >> 1][(nt & 1) * 2]);
#pragma unroll
            for (int np = 0; np < 4; np++)
                ldsm4(bl2[np], sb + OFF_BLO + rowB + np * 2048 + cB);
#pragma unroll
            for (int mt = 0; mt < 4; mt++)
#pragma unroll
                for (int nt = 0; nt < 8; nt++)
                    mma16816(acc[mt][nt], af[mt], &bl2[nt >> 1][(nt & 1) * 2]);
#pragma unroll
            for (int mt = 0; mt < 4; mt++)
                ldsm4(af[mt], sb + OFF_ALO + rowA + mt * 2048 + cA);
#pragma unroll
            for (int mt = 0; mt < 4; mt++)
#pragma unroll
                for (int nt = 0; nt < 8; nt++)
                    mma16816(acc[mt][nt], af[mt], &bh[nt >> 1][(nt & 1) * 2]);
        }
        __syncthreads();
    }

    // ---- epilogue: write partials (disjoint per CTA/warp) ----
    const int gq = lane >> 2;          // row within 8
    const int t2 = (lane & 3) * 2;     // col pair
    float* base = g_part + (size_t)z * (BS_ * G4_);
#pragma unroll
    for (int mt = 0; mt < 4; mt++)
#pragma unroll
        for (int nt = 0; nt < 8; nt++) {
            int row = mw + mt * 16 + gq;
            int col = nh * 128 + nw + nt * 8 + t2;
            *(float2*)(base + (size_t)row * G4_ + col) =
                make_float2(acc[mt][nt][0], acc[mt][nt][1]);
            *(float2*)(base + (size_t)(row + 8) * G4_ + col) =
                make_float2(acc[mt][nt][2], acc[mt][nt][3]);
        }
}

// ---------------------------------------------------------------------------
// Kernel 2b: reduce K-split partials into g_pg
// ---------------------------------------------------------------------------
__global__ __launch_bounds__(256) void reduce_k() {
    const int i = blockIdx.x * 256 + threadIdx.x;   // 65536 outputs
    float s0 = 0.f, s1 = 0.f, s2 = 0.f, s3 = 0.f;
#pragma unroll
    for (int zz = 0; zz < 72; zz += 4) {
        s0 += g_part[(size_t)(zz + 0) * 65536 + i];
        s1 += g_part[(size_t)(zz + 1) * 65536 + i];
        s2 += g_part[(size_t)(zz + 2) * 65536 + i];
        s3 += g_part[(size_t)(zz + 3) * 65536 + i];
    }
    s0 += g_part[(size_t)72 * 65536 + i];
    s1 += g_part[(size_t)73 * 65536 + i];
    g_pg[i] = (s0 + s1) + (s2 + s3);
}

// ---------------------------------------------------------------------------
// Kernel 3: LSTM recurrence (512 thr, W_hh in regs) + fused head GEMV
// ---------------------------------------------------------------------------
__global__ __launch_bounds__(512) void lstm_k(
    const float* __restrict__ W_hh, const float* __restrict__ b_ih,
    const float* __restrict__ b_hh, const float* __restrict__ W_head,
    const float* __restrict__ b_head, float* __restrict__ outp)
{
    __shared__ float hs[H_];
    __shared__ float gsh[G4_];

    const int t = threadIdx.x, b = blockIdx.x;
    const int g = t >> 1, half = t & 1;

    float w[32];
#pragma unroll
    for (int j = 0; j < 32; j++) w[j] = W_hh[g * H_ + half * 32 + j];
    const float bsum = b_ih[g] + b_hh[g];
    float cv = 0.f;
    if (t < H_) hs[t] = 0.f;
    float pgv = (half == 0) ? g_pg[(b * S_) * G4_ + g] : 0.f;
    __syncthreads();

    for (int s = 0; s < S_; s++) {
        float pgn = (half == 0 && s + 1 < S_)
                        ? g_pg[(b * S_ + s + 1) * G4_ + g] : 0.f;
        float a0 = 0.f, a1 = 0.f, a2 = 0.f, a3 = 0.f;
        const int hb = half * 32;
#pragma unroll
        for (int j = 0; j < 32; j += 4) {
            a0 = fmaf(w[j],     hs[hb + j],     a0);
            a1 = fmaf(w[j + 1], hs[hb + j + 1], a1);
            a2 = fmaf(w[j + 2], hs[hb + j + 2], a2);
            a3 = fmaf(w[j + 3], hs[hb + j + 3], a3);
        }
        float p = (a0 + a1) + (a2 + a3);
        p += __shfl_xor_sync(0xFFFFFFFFu, p, 1);
        if (half == 0) gsh[g] = p + pgv + bsum;
        __syncthreads();
        if (t < H_) {
            float ig = gsh[t], fg = gsh[H_ + t];
            float gg = gsh[2 * H_ + t], og = gsh[3 * H_ + t];
            float si = __fdividef(1.f, 1.f + __expf(-ig));
            float sf = __fdividef(1.f, 1.f + __expf(-fg));
            float so = __fdividef(1.f, 1.f + __expf(-og));
            float th = 1.f - __fdividef(2.f, __expf(2.f * gg) + 1.f);
            float c  = sf * cv + si * th;
            cv = c;
            hs[t] = so * (1.f - __fdividef(2.f, __expf(2.f * c) + 1.f));
        }
        __syncthreads();
        pgv = pgn;
    }

    for (int n = t; n < N_; n += 512) {
        const float4* wr = (const float4*)(W_head + (size_t)n * H_);
        float acc = b_head[n];
#pragma unroll
        for (int q = 0; q < 16; q++) {
            float4 v = wr[q];
            acc = fmaf(v.x, hs[q * 4],     acc);
            acc = fmaf(v.y, hs[q * 4 + 1], acc);
            acc = fmaf(v.z, hs[q * 4 + 2], acc);
            acc = fmaf(v.w, hs[q * 4 + 3], acc);
        }
        outp[b * N_ + n] = acc;
    }
}

// ---------------------------------------------------------------------------
extern "C" void kernel_launch(void* const* d_in, const int* in_sizes, int n_in,
                              void* d_out, int out_size)
{
    const float* x       = (const float*)d_in[0];
    const int*   ei      = (const int*)  d_in[1];
    const float* w_lin   = (const float*)d_in[2];
    const float* att_src = (const float*)d_in[3];
    const float* att_dst = (const float*)d_in[4];
    const float* gbias   = (const float*)d_in[5];
    const float* W_ih    = (const float*)d_in[6];
    const float* W_hh    = (const float*)d_in[7];
    const float* b_ih    = (const float*)d_in[8];
    const float* b_hh    = (const float*)d_in[9];
    const float* W_head  = (const float*)d_in[10];
    const float* b_head  = (const float*)d_in[11];
    float*       out     = (float*)d_out;
    const int    E       = in_sizes[1] / 2;

    static int smem_set = 0;
    if (!smem_set) {
        cudaFuncSetAttribute(gemm_k, cudaFuncAttributeMaxDynamicSharedMemorySize,
                             SMEM_TOT);
        smem_set = 1;
    }

    gat_k<<<BS_ / 2, 256>>>(x, ei, w_lin, att_src, att_dst, E);
    gemm_k<<<dim3(KSPLIT, NSPL), 256, SMEM_TOT>>>(W_ih, w_lin, gbias);
    reduce_k<<<(BS_ * G4_) / 256, 256>>>();
    lstm_k<<<B_, 512>>>(W_hh, b_ih, b_hh, W_head, b_head, out);
}

// round 12
// speedup vs baseline: 1.8778x; 1.0123x over previous
#include <cuda_runtime.h>
#include <cuda_bf16.h>
#include <cstdint>

// ---------------------------------------------------------------------------
#define B_   8
#define S_   32
#define N_   2000
#define GH_  32
#define H_   64
#define D_   64000          // N_*GH_
#define BS_  256
#define G4_  256

#define KSPLIT 74           // K-splits (chunks of 64 over D_)
#define NSPL   2            // gate halves (128 each)
#define NCHUNK 1000         // D_/64
#define NST    28           // staged agg nodes per CTA (2 per chunk, max 14 chunks)

__device__ float g_agg[BS_ * N_];                    // 2 MB
__device__ float g_pg[BS_ * G4_];                    // 256 KB pre-gates
__device__ float g_part[KSPLIT * BS_ * G4_];         // 19.4 MB GEMM partials

// ---------------------------------------------------------------------------
// helpers
// ---------------------------------------------------------------------------
__device__ __forceinline__ uint32_t smem_u32(const void* p) {
    uint32_t a;
    asm("{ .reg .u64 t; cvta.to.shared.u64 t, %1; cvt.u32.u64 %0, t; }"
        : "=r"(a) : "l"(p));
    return a;
}
// SW128-style swizzle (permutes 16B chunks within a 128B row by row%8)
#define SWZ(o) ((o) ^ (((o) >> 3) & 0x70))

__device__ __forceinline__ void ldsm4(uint32_t* r, uint32_t addr) {
    asm volatile("ldmatrix.sync.aligned.m8n8.x4.shared.b16 {%0,%1,%2,%3}, [%4];"
                 : "=r"(r[0]), "=r"(r[1]), "=r"(r[2]), "=r"(r[3]) : "r"(addr));
}
__device__ __forceinline__ void mma16816(float* c, const uint32_t* a,
                                         const uint32_t* b) {
    asm volatile(
        "mma.sync.aligned.m16n8k16.row.col.f32.bf16.bf16.f32 "
        "{%0,%1,%2,%3}, {%4,%5,%6,%7}, {%8,%9}, {%0,%1,%2,%3};"
        : "+f"(c[0]), "+f"(c[1]), "+f"(c[2]), "+f"(c[3])
        : "r"(a[0]), "r"(a[1]), "r"(a[2]), "r"(a[3]), "r"(b[0]), "r"(b[1]));
}

// ---------------------------------------------------------------------------
// Kernel 1: GAT — single edge pass, 2 bs-rows per CTA. Writes agg only.
// ---------------------------------------------------------------------------
__global__ __launch_bounds__(256) void gat_k(
    const float* __restrict__ x, const int* __restrict__ ei,
    const float* __restrict__ w_lin, const float* __restrict__ att_src,
    const float* __restrict__ att_dst, int E)
{
    __shared__ float xs[2][N_];
    __shared__ float den[2][N_];
    __shared__ float num[2][N_];

    const int bs0 = blockIdx.x * 2;
    const int tid = threadIdx.x;

    for (int n = tid; n < N_; n += 256) {
        xs[0][n] = x[(size_t)bs0 * N_ + n];
        xs[1][n] = x[(size_t)(bs0 + 1) * N_ + n];
        den[0][n] = 0.f; den[1][n] = 0.f;
        num[0][n] = 0.f; num[1][n] = 0.f;
    }
    float cs = 0.f, cd = 0.f;
    for (int g = 0; g < GH_; g++) {
        float w = w_lin[g];
        cs = fmaf(w, att_src[g], cs);
        cd = fmaf(w, att_dst[g], cd);
    }
    __syncthreads();

    const int Et = E + N_;
    for (int t = tid; t < Et; t += 256) {
        int s, d;
        if (t < E) { s = ei[t]; d = ei[E + t]; } else { s = t - E; d = s; }
        float x0s = xs[0][s], x0d = xs[0][d];
        float x1s = xs[1][s], x1d = xs[1][d];
        float z0 = cs * x0s + cd * x0d;
        float z1 = cs * x1s + cd * x1d;
        float e0 = (z0 > 0.f) ? z0 : 0.2f * z0;
        float e1 = (z1 > 0.f) ? z1 : 0.2f * z1;
        float w0 = __expf(e0);
        float w1 = __expf(e1);
        atomicAdd(&den[0][d], w0);
        atomicAdd(&num[0][d], w0 * x0s);
        atomicAdd(&den[1][d], w1);
        atomicAdd(&num[1][d], w1 * x1s);
    }
    __syncthreads();

    for (int n = tid; n < N_; n += 256) {
        g_agg[(size_t)bs0 * N_ + n]       = num[0][n] / den[0][n];
        g_agg[(size_t)(bs0 + 1) * N_ + n] = num[1][n] / den[1][n];
    }
}

// ---------------------------------------------------------------------------
// Kernel 2: bf16 hi/lo GEMM via mma.sync (HMMA). pg = A[256,64000]*W^T.
//   grid (74 K-splits, 2 gate-halves). CTA tile 256x128, warp tile 64x64.
//   A generated on the fly from agg; partials to g_part (no atomics).
// ---------------------------------------------------------------------------
#define OFF_WL   0
#define OFF_GB   128
#define OFF_AGG  256                       // 256*28*4 = 28672
#define OFF_AHI  29056                     // 256x64 bf16 = 32768
#define OFF_ALO  61824
#define OFF_BHI  94592                     // 128x64 bf16 = 16384
#define OFF_BLO  110976
#define SMEM_TOT 127360

__global__ __launch_bounds__(256) void gemm_k(
    const float* __restrict__ W_ih,
    const float* __restrict__ w_lin_g, const float* __restrict__ gbias_g)
{
    extern __shared__ __align__(128) char sm[];
    const uint32_t sb = smem_u32(sm);
    const int tid  = threadIdx.x;
    const int lane = tid & 31;
    const int wid  = tid >> 5;
    const int z    = blockIdx.x;           // K split
    const int nh   = blockIdx.y;           // gate half
    const int c0   = z * NCHUNK / KSPLIT;
    const int c1   = (z + 1) * NCHUNK / KSPLIT;
    const int n0   = c0 * 2;

    if (tid < 32) {
        ((float*)(sm + OFF_WL))[tid] = w_lin_g[tid];
        ((float*)(sm + OFF_GB))[tid] = gbias_g[tid];
    }
    for (int i = tid; i < 256 * NST; i += 256) {
        int row = i / NST, nl = i % NST;
        ((float*)(sm + OFF_AGG))[i] = g_agg[(size_t)row * N_ + n0 + nl];
    }
    __syncthreads();

    const float* wl = (const float*)(sm + OFF_WL);
    const float* gb = (const float*)(sm + OFF_GB);
    const float* ag = (const float*)(sm + OFF_AGG);

    // warp tile: 64x64; CTA = 4x2 warp grid over 256x128
    const int mw = (wid & 3) * 64;
    const int nw = (wid >> 2) * 64;

    // per-lane ldmatrix row components
    const uint32_t rowA = (uint32_t)(mw + (lane & 15)) * 128u;
    const uint32_t khA  = (uint32_t)(lane >> 4);
    const uint32_t swA  = (uint32_t)(lane & 7);
    const uint32_t rowB = (uint32_t)(nw + (lane & 7) + ((lane >> 4) << 3)) * 128u;
    const uint32_t khB  = (uint32_t)((lane >> 3) & 1);
    const uint32_t swB  = (uint32_t)(lane & 7);

    float acc[4][8][4];
#pragma unroll
    for (int mt = 0; mt < 4; mt++)
#pragma unroll
        for (int nt = 0; nt < 8; nt++)
#pragma unroll
            for (int q = 0; q < 4; q++) acc[mt][nt][q] = 0.f;

    for (int c = c0; c < c1; c++) {
        // ---- generate A tile (256x64 bf16 hi/lo) from agg ----
        const int cl2 = (c - c0) * 2;
#pragma unroll
        for (int i = 0; i < 16; i++) {
            int idx = tid + i * 256;
            int row = idx >> 4, c4 = idx & 15;
            float a  = ag[row * NST + cl2 + (c4 >> 3)];
            int   g0 = (c4 & 7) * 4;
            __nv_bfloat16 hi[4], lo[4];
#pragma unroll
            for (int j = 0; j < 4; j++) {
                float v = fmaxf(fmaf(a, wl[g0 + j], gb[g0 + j]), 0.f);
                hi[j] = __float2bfloat16_rn(v);
                lo[j] = __float2bfloat16_rn(v - __bfloat162float(hi[j]));
            }
            uint32_t off = SWZ((uint32_t)(row * 128 + c4 * 8));
            *(uint2*)(sm + OFF_AHI + off) = *(uint2*)hi;
            *(uint2*)(sm + OFF_ALO + off) = *(uint2*)lo;
        }
        // ---- load + convert W tile (128x64) ----
#pragma unroll
        for (int i = 0; i < 8; i++) {
            int idx = tid + i * 256;
            int row = idx >> 4, c4 = idx & 15;
            float4 w = *(const float4*)(W_ih + (size_t)(nh * 128 + row) * D_ +
                                        c * 64 + c4 * 4);
            float v[4] = {w.x, w.y, w.z, w.w};
            __nv_bfloat16 hi[4], lo[4];
#pragma unroll
            for (int j = 0; j < 4; j++) {
                hi[j] = __float2bfloat16_rn(v[j]);
                lo[j] = __float2bfloat16_rn(v[j] - __bfloat162float(hi[j]));
            }
            uint32_t off = SWZ((uint32_t)(row * 128 + c4 * 8));
            *(uint2*)(sm + OFF_BHI + off) = *(uint2*)hi;
            *(uint2*)(sm + OFF_BLO + off) = *(uint2*)lo;
        }
        __syncthreads();

        // ---- mma over 4 k16 steps, 3 hi/lo terms ----
#pragma unroll
        for (int ks = 0; ks < 4; ks++) {
            uint32_t af[4][4], bh[4][4], bl2[4][4];
            const uint32_t cA = (((uint32_t)(ks * 2) + khA) ^ swA) << 4;
            const uint32_t cB = (((uint32_t)(ks * 2) + khB) ^ swB) << 4;
#pragma unroll
            for (int mt = 0; mt < 4; mt++)
                ldsm4(af[mt], sb + OFF_AHI + rowA + mt * 2048 + cA);
#pragma unroll
            for (int np = 0; np < 4; np++)
                ldsm4(bh[np], sb + OFF_BHI + rowB + np * 2048 + cB);
#pragma unroll
            for (int mt = 0; mt < 4; mt++)
#pragma unroll
                for (int nt = 0; nt < 8; nt++)
                    mma16816(acc[mt][nt], af[mt], &bh[nt >> 1][(nt & 1) * 2]);
#pragma unroll
            for (int np = 0; np < 4; np++)
                ldsm4(bl2[np], sb + OFF_BLO + rowB + np * 2048 + cB);
#pragma unroll
            for (int mt = 0; mt < 4; mt++)
#pragma unroll
                for (int nt = 0; nt < 8; nt++)
                    mma16816(acc[mt][nt], af[mt], &bl2[nt >> 1][(nt & 1) * 2]);
#pragma unroll
            for (int mt = 0; mt < 4; mt++)
                ldsm4(af[mt], sb + OFF_ALO + rowA + mt * 2048 + cA);
#pragma unroll
            for (int mt = 0; mt < 4; mt++)
#pragma unroll
                for (int nt = 0; nt < 8; nt++)
                    mma16816(acc[mt][nt], af[mt], &bh[nt >> 1][(nt & 1) * 2]);
        }
        __syncthreads();
    }

    // ---- epilogue: write partials (disjoint per CTA/warp) ----
    const int gq = lane >> 2;          // row within 8
    const int t2 = (lane & 3) * 2;     // col pair
    float* base = g_part + (size_t)z * (BS_ * G4_);
#pragma unroll
    for (int mt = 0; mt < 4; mt++)
#pragma unroll
        for (int nt = 0; nt < 8; nt++) {
            int row = mw + mt * 16 + gq;
            int col = nh * 128 + nw + nt * 8 + t2;
            *(float2*)(base + (size_t)row * G4_ + col) =
                make_float2(acc[mt][nt][0], acc[mt][nt][1]);
            *(float2*)(base + (size_t)(row + 8) * G4_ + col) =
                make_float2(acc[mt][nt][2], acc[mt][nt][3]);
        }
}

// ---------------------------------------------------------------------------
// Kernel 2b: reduce K-split partials into g_pg
// ---------------------------------------------------------------------------
__global__ __launch_bounds__(256) void reduce_k() {
    const int i = blockIdx.x * 256 + threadIdx.x;   // 65536 outputs
    float s0 = 0.f, s1 = 0.f, s2 = 0.f, s3 = 0.f;
#pragma unroll
    for (int zz = 0; zz < 72; zz += 4) {
        s0 += g_part[(size_t)(zz + 0) * 65536 + i];
        s1 += g_part[(size_t)(zz + 1) * 65536 + i];
        s2 += g_part[(size_t)(zz + 2) * 65536 + i];
        s3 += g_part[(size_t)(zz + 3) * 65536 + i];
    }
    s0 += g_part[(size_t)72 * 65536 + i];
    s1 += g_part[(size_t)73 * 65536 + i];
    g_pg[i] = (s0 + s1) + (s2 + s3);
}

// ---------------------------------------------------------------------------
// Kernel 3: LSTM recurrence (512 thr, W_hh in regs) + fused head GEMV
// ---------------------------------------------------------------------------
__global__ __launch_bounds__(512) void lstm_k(
    const float* __restrict__ W_hh, const float* __restrict__ b_ih,
    const float* __restrict__ b_hh, const float* __restrict__ W_head,
    const float* __restrict__ b_head, float* __restrict__ outp)
{
    __shared__ float hs[H_];
    __shared__ float gsh[G4_];

    const int t = threadIdx.x, b = blockIdx.x;
    const int g = t >> 1, half = t & 1;

    float w[32];
#pragma unroll
    for (int j = 0; j < 32; j++) w[j] = W_hh[g * H_ + half * 32 + j];
    const float bsum = b_ih[g] + b_hh[g];
    float cv = 0.f;
    if (t < H_) hs[t] = 0.f;
    float pgv = (half == 0) ? g_pg[(b * S_) * G4_ + g] : 0.f;
    __syncthreads();

    for (int s = 0; s < S_; s++) {
        float pgn = (half == 0 && s + 1 < S_)
                        ? g_pg[(b * S_ + s + 1) * G4_ + g] : 0.f;
        float a0 = 0.f, a1 = 0.f, a2 = 0.f, a3 = 0.f;
        const int hb = half * 32;
#pragma unroll
        for (int j = 0; j < 32; j += 4) {
            a0 = fmaf(w[j],     hs[hb + j],     a0);
            a1 = fmaf(w[j + 1], hs[hb + j + 1], a1);
            a2 = fmaf(w[j + 2], hs[hb + j + 2], a2);
            a3 = fmaf(w[j + 3], hs[hb + j + 3], a3);
        }
        float p = (a0 + a1) + (a2 + a3);
        p += __shfl_xor_sync(0xFFFFFFFFu, p, 1);
        if (half == 0) gsh[g] = p + pgv + bsum;
        __syncthreads();
        if (t < H_) {
            float ig = gsh[t], fg = gsh[H_ + t];
            float gg = gsh[2 * H_ + t], og = gsh[3 * H_ + t];
            float si = __fdividef(1.f, 1.f + __expf(-ig));
            float sf = __fdividef(1.f, 1.f + __expf(-fg));
            float so = __fdividef(1.f, 1.f + __expf(-og));
            float th = 1.f - __fdividef(2.f, __expf(2.f * gg) + 1.f);
            float c  = sf * cv + si * th;
            cv = c;
            hs[t] = so * (1.f - __fdividef(2.f, __expf(2.f * c) + 1.f));
        }
        __syncthreads();
        pgv = pgn;
    }

    for (int n = t; n < N_; n += 512) {
        const float4* wr = (const float4*)(W_head + (size_t)n * H_);
        float acc = b_head[n];
#pragma unroll
        for (int q = 0; q < 16; q++) {
            float4 v = wr[q];
            acc = fmaf(v.x, hs[q * 4],     acc);
            acc = fmaf(v.y, hs[q * 4 + 1], acc);
            acc = fmaf(v.z, hs[q * 4 + 2], acc);
            acc = fmaf(v.w, hs[q * 4 + 3], acc);
        }
        outp[b * N_ + n] = acc;
    }
}

// ---------------------------------------------------------------------------
extern "C" void kernel_launch(void* const* d_in, const int* in_sizes, int n_in,
                              void* d_out, int out_size)
{
    const float* x       = (const float*)d_in[0];
    const int*   ei      = (const int*)  d_in[1];
    const float* w_lin   = (const float*)d_in[2];
    const float* att_src = (const float*)d_in[3];
    const float* att_dst = (const float*)d_in[4];
    const float* gbias   = (const float*)d_in[5];
    const float* W_ih    = (const float*)d_in[6];
    const float* W_hh    = (const float*)d_in[7];
    const float* b_ih    = (const float*)d_in[8];
    const float* b_hh    = (const float*)d_in[9];
    const float* W_head  = (const float*)d_in[10];
    const float* b_head  = (const float*)d_in[11];
    float*       out     = (float*)d_out;
    const int    E       = in_sizes[1] / 2;

    static int smem_set = 0;
    if (!smem_set) {
        cudaFuncSetAttribute(gemm_k, cudaFuncAttributeMaxDynamicSharedMemorySize,
                             SMEM_TOT);
        smem_set = 1;
    }

    gat_k<<<BS_ / 2, 256>>>(x, ei, w_lin, att_src, att_dst, E);
    gemm_k<<<dim3(KSPLIT, NSPL), 256, SMEM_TOT>>>(W_ih, w_lin, gbias);
    reduce_k<<<(BS_ * G4_) / 256, 256>>>();
    lstm_k<<<B_, 512>>>(W_hh, b_ih, b_hh, W_head, b_head, out);
}

// round 13
// speedup vs baseline: 2.8752x; 1.5312x over previous
#include <cuda_runtime.h>
#include <cuda_bf16.h>
#include <cstdint>

// ---------------------------------------------------------------------------
#define B_   8
#define S_   32
#define N_   2000
#define GH_  32
#define H_   64
#define D_   64000          // N_*GH_
#define BS_  256
#define G4_  256

#define KSPLIT 74           // K-splits (each ~13.5 chunks of 64 over D_)
#define NSPL   2            // gate halves (128 each)
#define NCHUNK 1000         // D_/64
#define NST    28           // staged agg nodes per CTA (2 per chunk, max 14 chunks)

__device__ float g_agg[BS_ * N_];                    // 2 MB
__device__ float g_pg[BS_ * G4_];                    // 256 KB pre-gates
__device__ float g_part[KSPLIT * BS_ * G4_];         // 19.4 MB GEMM partials
// CSR scratch (edge list sorted by dst, rebuilt every call)
__device__ int   g_cnt[N_];
__device__ int   g_off[N_ + 1];
__device__ int   g_cur[N_];
__device__ int   g_src[131072];

// ---------------------------------------------------------------------------
// helpers
// ---------------------------------------------------------------------------
__device__ __forceinline__ uint32_t smem_u32(const void* p) {
    uint32_t a;
    asm("{ .reg .u64 t; cvta.to.shared.u64 t, %1; cvt.u32.u64 %0, t; }"
        : "=r"(a) : "l"(p));
    return a;
}
#define SWZ(o) ((o) ^ (((o) >> 3) & 0x70))

__device__ __forceinline__ void ldsm4(uint32_t* r, uint32_t addr) {
    asm volatile("ldmatrix.sync.aligned.m8n8.x4.shared.b16 {%0,%1,%2,%3}, [%4];"
                 : "=r"(r[0]), "=r"(r[1]), "=r"(r[2]), "=r"(r[3]) : "r"(addr));
}
__device__ __forceinline__ void mma16816(float* c, const uint32_t* a,
                                         const uint32_t* b) {
    asm volatile(
        "mma.sync.aligned.m16n8k16.row.col.f32.bf16.bf16.f32 "
        "{%0,%1,%2,%3}, {%4,%5,%6,%7}, {%8,%9}, {%0,%1,%2,%3};"
        : "+f"(c[0]), "+f"(c[1]), "+f"(c[2]), "+f"(c[3])
        : "r"(a[0]), "r"(a[1]), "r"(a[2]), "r"(a[3]), "r"(b[0]), "r"(b[1]));
}
__device__ __forceinline__ float sigm_f(float v) {
    return __fdividef(1.f, 1.f + __expf(-v));
}
__device__ __forceinline__ float tanh_f(float v) {
    return 1.f - __fdividef(2.f, __expf(2.f * v) + 1.f);
}

// ---------------------------------------------------------------------------
// CSR build: zero counts -> histogram(dst) -> scan -> scatter(src)
// Self-loops NOT in CSR (handled explicitly in the gather).
// ---------------------------------------------------------------------------
__global__ void zero_cnt_k() {
    int i = blockIdx.x * 256 + threadIdx.x;
    if (i < N_) g_cnt[i] = 0;
}
__global__ void hist_k(const int* __restrict__ ei, int E) {
    int t = blockIdx.x * 256 + threadIdx.x;
    if (t < E) atomicAdd(&g_cnt[ei[E + t]], 1);
}
__global__ __launch_bounds__(512) void scan_k(int E) {
    __shared__ int wsum[16];
    const int t = threadIdx.x, lane = t & 31, wid = t >> 5;
    int v[4];
    const int base = t * 4;
#pragma unroll
    for (int j = 0; j < 4; j++)
        v[j] = (base + j < N_) ? g_cnt[base + j] : 0;
    int s = v[0] + v[1] + v[2] + v[3];
    int ps = s;
#pragma unroll
    for (int d = 1; d < 32; d <<= 1) {
        int o = __shfl_up_sync(0xFFFFFFFFu, ps, d);
        if (lane >= d) ps += o;
    }
    if (lane == 31) wsum[wid] = ps;
    __syncthreads();
    if (t < 16) {
        int w = wsum[t];
#pragma unroll
        for (int d = 1; d < 16; d <<= 1) {
            int o = __shfl_up_sync(0x0000FFFFu, w, d);
            if (t >= d) w += o;
        }
        wsum[t] = w;
    }
    __syncthreads();
    int run = ((wid > 0) ? wsum[wid - 1] : 0) + ps - s;
#pragma unroll
    for (int j = 0; j < 4; j++) {
        if (base + j < N_) {
            g_off[base + j] = run;
            g_cur[base + j] = run;
            run += v[j];
        }
    }
    if (t == 511) g_off[N_] = E;
}
__global__ void scat_k(const int* __restrict__ ei, int E) {
    int t = blockIdx.x * 256 + threadIdx.x;
    if (t < E) {
        int d = ei[E + t];
        int pos = atomicAdd(&g_cur[d], 1);
        g_src[pos] = ei[t];
    }
}

// ---------------------------------------------------------------------------
// Kernel 1: GAT gather — no atomics, no per-edge expf.
//   exp(leaky(z)) factors: z>0 -> u[s]*vd,  z<0 -> u2[s]*vd2, with
//   u=exp(cs*x), u2=exp(0.2*cs*x) per src node; vd,vd2 per dst node.
//   2 bs-rows per CTA. Writes agg only.
// ---------------------------------------------------------------------------
__global__ __launch_bounds__(256) void gat_k(
    const float* __restrict__ x, const float* __restrict__ w_lin,
    const float* __restrict__ att_src, const float* __restrict__ att_dst)
{
    __shared__ float xs[2][N_];          // 16 KB
    __shared__ float ue[2][2][N_];       // 32 KB: [row][pos/neg][node]

    const int bs0 = blockIdx.x * 2;
    const int tid = threadIdx.x;

    float cs = 0.f, cd = 0.f;
    for (int g = 0; g < GH_; g++) {
        float w = w_lin[g];
        cs = fmaf(w, att_src[g], cs);
        cd = fmaf(w, att_dst[g], cd);
    }
    for (int n = tid; n < N_; n += 256) {
        float x0 = x[(size_t)bs0 * N_ + n];
        float x1 = x[(size_t)(bs0 + 1) * N_ + n];
        xs[0][n] = x0;
        xs[1][n] = x1;
        ue[0][0][n] = __expf(cs * x0);
        ue[0][1][n] = __expf(0.2f * cs * x0);
        ue[1][0][n] = __expf(cs * x1);
        ue[1][1][n] = __expf(0.2f * cs * x1);
    }
    __syncthreads();

    for (int n = tid; n < N_; n += 256) {
        const int off = g_off[n], end = g_off[n + 1];
        const float x0d = xs[0][n], x1d = xs[1][n];
        const float cz0 = cd * x0d, cz1 = cd * x1d;
        const float vd0 = __expf(cz0),        vd1 = __expf(cz1);
        const float vq0 = __expf(0.2f * cz0), vq1 = __expf(0.2f * cz1);

        // self loop (src = dst = n)
        float z0 = cs * x0d + cz0;
        float z1 = cs * x1d + cz1;
        float w0 = (z0 > 0.f) ? ue[0][0][n] * vd0 : ue[0][1][n] * vq0;
        float w1 = (z1 > 0.f) ? ue[1][0][n] * vd1 : ue[1][1][n] * vq1;
        float den0 = w0, num0 = w0 * x0d;
        float den1 = w1, num1 = w1 * x1d;

        for (int p = off; p < end; p++) {
            int s = g_src[p];
            float x0s = xs[0][s];
            float x1s = xs[1][s];
            float za = cs * x0s + cz0;
            float zb = cs * x1s + cz1;
            float wa = (za > 0.f) ? ue[0][0][s] * vd0 : ue[0][1][s] * vq0;
            float wb = (zb > 0.f) ? ue[1][0][s] * vd1 : ue[1][1][s] * vq1;
            den0 += wa; num0 = fmaf(wa, x0s, num0);
            den1 += wb; num1 = fmaf(wb, x1s, num1);
        }
        g_agg[(size_t)bs0 * N_ + n]       = __fdividef(num0, den0);
        g_agg[(size_t)(bs0 + 1) * N_ + n] = __fdividef(num1, den1);
    }
}

// ---------------------------------------------------------------------------
// Kernel 2: bf16 hi/lo GEMM via mma.sync, DOUBLE-BUFFERED smem tiles.
//   grid (74 K-splits, 2 gate-halves). CTA tile 256x128, warp tile 64x64.
// ---------------------------------------------------------------------------
#define OFF_WL   0
#define OFF_GB   128
#define OFF_AGG  256                       // 256*28*4 = 28672 -> ends 28928
#define OFF_A0H  28928
#define OFF_A0L  61696
#define OFF_B0H  94464
#define OFF_B0L  110848
#define OFF_A1H  127232
#define OFF_A1L  160000
#define OFF_B1H  192768
#define OFF_B1L  209152
#define SMEM_TOT 225536

__device__ __forceinline__ void conv_tiles(
    char* sm, uint32_t oAH, uint32_t oAL, uint32_t oBH, uint32_t oBL,
    const float* wl, const float* gb, const float* ag,
    const float* __restrict__ W_ih, int nh, int c, int cl2, int tid)
{
    // A tile (256x64 bf16 hi/lo) generated from agg
#pragma unroll
    for (int i = 0; i < 16; i++) {
        int idx = tid + i * 256;
        int row = idx >> 4, c4 = idx & 15;
        float a  = ag[row * NST + cl2 + (c4 >> 3)];
        int   g0 = (c4 & 7) * 4;
        __nv_bfloat16 hi[4], lo[4];
#pragma unroll
        for (int j = 0; j < 4; j++) {
            float v = fmaxf(fmaf(a, wl[g0 + j], gb[g0 + j]), 0.f);
            hi[j] = __float2bfloat16_rn(v);
            lo[j] = __float2bfloat16_rn(v - __bfloat162float(hi[j]));
        }
        uint32_t off = SWZ((uint32_t)(row * 128 + c4 * 8));
        *(uint2*)(sm + oAH + off) = *(uint2*)hi;
        *(uint2*)(sm + oAL + off) = *(uint2*)lo;
    }
    // B tile (128x64) from W_ih
#pragma unroll
    for (int i = 0; i < 8; i++) {
        int idx = tid + i * 256;
        int row = idx >> 4, c4 = idx & 15;
        float4 w = *(const float4*)(W_ih + (size_t)(nh * 128 + row) * D_ +
                                    c * 64 + c4 * 4);
        float v[4] = {w.x, w.y, w.z, w.w};
        __nv_bfloat16 hi[4], lo[4];
#pragma unroll
        for (int j = 0; j < 4; j++) {
            hi[j] = __float2bfloat16_rn(v[j]);
            lo[j] = __float2bfloat16_rn(v[j] - __bfloat162float(hi[j]));
        }
        uint32_t off = SWZ((uint32_t)(row * 128 + c4 * 8));
        *(uint2*)(sm + oBH + off) = *(uint2*)hi;
        *(uint2*)(sm + oBL + off) = *(uint2*)lo;
    }
}

__global__ __launch_bounds__(256) void gemm_k(
    const float* __restrict__ W_ih,
    const float* __restrict__ w_lin_g, const float* __restrict__ gbias_g)
{
    extern __shared__ __align__(128) char sm[];
    const uint32_t sb = smem_u32(sm);
    const int tid  = threadIdx.x;
    const int lane = tid & 31;
    const int wid  = tid >> 5;
    const int z    = blockIdx.x;           // K split
    const int nh   = blockIdx.y;           // gate half
    const int c0   = z * NCHUNK / KSPLIT;
    const int c1   = (z + 1) * NCHUNK / KSPLIT;
    const int n0   = c0 * 2;

    if (tid < 32) {
        ((float*)(sm + OFF_WL))[tid] = w_lin_g[tid];
        ((float*)(sm + OFF_GB))[tid] = gbias_g[tid];
    }
    for (int i = tid; i < 256 * NST; i += 256) {
        int row = i / NST, nl = i % NST;
        ((float*)(sm + OFF_AGG))[i] = g_agg[(size_t)row * N_ + n0 + nl];
    }
    __syncthreads();

    const float* wl = (const float*)(sm + OFF_WL);
    const float* gb = (const float*)(sm + OFF_GB);
    const float* ag = (const float*)(sm + OFF_AGG);

    const uint32_t AH[2] = {OFF_A0H, OFF_A1H};
    const uint32_t AL[2] = {OFF_A0L, OFF_A1L};
    const uint32_t BH[2] = {OFF_B0H, OFF_B1H};
    const uint32_t BL[2] = {OFF_B0L, OFF_B1L};

    const int mw = (wid & 3) * 64;
    const int nw = (wid >> 2) * 64;

    const uint32_t rowA = (uint32_t)(mw + (lane & 15)) * 128u;
    const uint32_t khA  = (uint32_t)(lane >> 4);
    const uint32_t swA  = (uint32_t)(lane & 7);
    const uint32_t rowB = (uint32_t)(nw + (lane & 7) + ((lane >> 4) << 3)) * 128u;
    const uint32_t khB  = (uint32_t)((lane >> 3) & 1);
    const uint32_t swB  = (uint32_t)(lane & 7);

    float acc[4][8][4];
#pragma unroll
    for (int mt = 0; mt < 4; mt++)
#pragma unroll
        for (int nt = 0; nt < 8; nt++)
#pragma unroll
            for (int q = 0; q < 4; q++) acc[mt][nt][q] = 0.f;

    // prologue: fill buffer 0
    conv_tiles(sm, AH[0], AL[0], BH[0], BL[0], wl, gb, ag, W_ih, nh, c0, 0, tid);
    __syncthreads();

    for (int c = c0; c < c1; c++) {
        const int st = (c - c0) & 1;
        if (c + 1 < c1)
            conv_tiles(sm, AH[st ^ 1], AL[st ^ 1], BH[st ^ 1], BL[st ^ 1],
                       wl, gb, ag, W_ih, nh, c + 1, (c + 1 - c0) * 2, tid);

        const uint32_t bAH = sb + AH[st], bAL = sb + AL[st];
        const uint32_t bBH = sb + BH[st], bBL = sb + BL[st];
#pragma unroll
        for (int ks = 0; ks < 4; ks++) {
            uint32_t af[4][4], bh[4][4], bl2[4][4];
            const uint32_t cA = (((uint32_t)(ks * 2) + khA) ^ swA) << 4;
            const uint32_t cB = (((uint32_t)(ks * 2) + khB) ^ swB) << 4;
#pragma unroll
            for (int mt = 0; mt < 4; mt++)
                ldsm4(af[mt], bAH + rowA + mt * 2048 + cA);
#pragma unroll
            for (int np = 0; np < 4; np++)
                ldsm4(bh[np], bBH + rowB + np * 2048 + cB);
#pragma unroll
            for (int mt = 0; mt < 4; mt++)
#pragma unroll
                for (int nt = 0; nt < 8; nt++)
                    mma16816(acc[mt][nt], af[mt], &bh[nt >> 1][(nt & 1) * 2]);
#pragma unroll
            for (int np = 0; np < 4; np++)
                ldsm4(bl2[np], bBL + rowB + np * 2048 + cB);
#pragma unroll
            for (int mt = 0; mt < 4; mt++)
#pragma unroll
                for (int nt = 0; nt < 8; nt++)
                    mma16816(acc[mt][nt], af[mt], &bl2[nt >> 1][(nt & 1) * 2]);
#pragma unroll
            for (int mt = 0; mt < 4; mt++)
                ldsm4(af[mt], bAL + rowA + mt * 2048 + cA);
#pragma unroll
            for (int mt = 0; mt < 4; mt++)
#pragma unroll
                for (int nt = 0; nt < 8; nt++)
                    mma16816(acc[mt][nt], af[mt], &bh[nt >> 1][(nt & 1) * 2]);
        }
        __syncthreads();
    }

    // epilogue: disjoint partial writes
    const int gq = lane >> 2;
    const int t2 = (lane & 3) * 2;
    float* base = g_part + (size_t)z * (BS_ * G4_);
#pragma unroll
    for (int mt = 0; mt < 4; mt++)
#pragma unroll
        for (int nt = 0; nt < 8; nt++) {
            int row = mw + mt * 16 + gq;
            int col = nh * 128 + nw + nt * 8 + t2;
            *(float2*)(base + (size_t)row * G4_ + col) =
                make_float2(acc[mt][nt][0], acc[mt][nt][1]);
            *(float2*)(base + (size_t)(row + 8) * G4_ + col) =
                make_float2(acc[mt][nt][2], acc[mt][nt][3]);
        }
}

// ---------------------------------------------------------------------------
// Kernel 2b: reduce K-split partials into g_pg
// ---------------------------------------------------------------------------
__global__ __launch_bounds__(256) void reduce_k() {
    const int i = blockIdx.x * 256 + threadIdx.x;
    float s0 = 0.f, s1 = 0.f, s2 = 0.f, s3 = 0.f;
#pragma unroll
    for (int zz = 0; zz < 72; zz += 4) {
        s0 += g_part[(size_t)(zz + 0) * 65536 + i];
        s1 += g_part[(size_t)(zz + 1) * 65536 + i];
        s2 += g_part[(size_t)(zz + 2) * 65536 + i];
        s3 += g_part[(size_t)(zz + 3) * 65536 + i];
    }
    s0 += g_part[(size_t)72 * 65536 + i];
    s1 += g_part[(size_t)73 * 65536 + i];
    g_pg[i] = (s0 + s1) + (s2 + s3);
}

// ---------------------------------------------------------------------------
// Kernel 3: LSTM recurrence, 128 threads: pair (lane, lane^1) owns h-index j,
//   gates (i,g)/(f,o). W_hh rows in registers, shfl exchange, h double-buffered
//   -> ONE __syncthreads per step. Fused head GEMV.
// ---------------------------------------------------------------------------
__global__ __launch_bounds__(128) void lstm_k(
    const float* __restrict__ W_hh, const float* __restrict__ b_ih,
    const float* __restrict__ b_hh, const float* __restrict__ W_head,
    const float* __restrict__ b_head, float* __restrict__ outp)
{
    __shared__ __align__(16) float hs[2][H_];

    const int t = threadIdx.x, b = blockIdx.x;
    const int j = t >> 1, p = t & 1;
    const int r0 = (p == 0) ? j          : H_ + j;      // i | f
    const int r1 = (p == 0) ? 2 * H_ + j : 3 * H_ + j;  // g | o

    float w0[H_], w1[H_];
#pragma unroll
    for (int k = 0; k < H_; k++) {
        w0[k] = W_hh[r0 * H_ + k];
        w1[k] = W_hh[r1 * H_ + k];
    }
    const float bias0 = b_ih[r0] + b_hh[r0];
    const float bias1 = b_ih[r1] + b_hh[r1];
    float cval = 0.f;
    if (p == 1) hs[0][j] = 0.f;
    float pg0 = g_pg[(b * S_) * G4_ + r0];
    float pg1 = g_pg[(b * S_) * G4_ + r1];
    __syncthreads();

    for (int s = 0; s < S_; s++) {
        float pn0 = 0.f, pn1 = 0.f;
        if (s + 1 < S_) {
            pn0 = g_pg[(b * S_ + s + 1) * G4_ + r0];
            pn1 = g_pg[(b * S_ + s + 1) * G4_ + r1];
        }
        const float4* h4 = (const float4*)(hs[s & 1]);
        float a0 = 0.f, a1 = 0.f, a2 = 0.f, a3 = 0.f;
        float d0 = 0.f, d1 = 0.f, d2 = 0.f, d3 = 0.f;
#pragma unroll
        for (int k = 0; k < 16; k++) {
            float4 hv = h4[k];
            a0 = fmaf(w0[4 * k],     hv.x, a0);
            a1 = fmaf(w0[4 * k + 1], hv.y, a1);
            a2 = fmaf(w0[4 * k + 2], hv.z, a2);
            a3 = fmaf(w0[4 * k + 3], hv.w, a3);
            d0 = fmaf(w1[4 * k],     hv.x, d0);
            d1 = fmaf(w1[4 * k + 1], hv.y, d1);
            d2 = fmaf(w1[4 * k + 2], hv.z, d2);
            d3 = fmaf(w1[4 * k + 3], hv.w, d3);
        }
        float g0 = (a0 + a1) + (a2 + a3) + pg0 + bias0;
        float g1 = (d0 + d1) + (d2 + d3) + pg1 + bias1;

        float s0 = sigm_f(g0);                         // sig(i) | sig(f)
        float s1 = (p == 0) ? tanh_f(g1) : sigm_f(g1); // tanh(g) | sig(o)
        float prod  = s0 * s1;                         // p0: si*tg
        float other = __shfl_xor_sync(0xFFFFFFFFu, prod, 1);
        if (p == 1) {
            cval = fmaf(s0, cval, other);              // c = sf*c + si*tg
            hs[(s + 1) & 1][j] = s1 * tanh_f(cval);    // h = so*tanh(c)
        }
        __syncthreads();
        pg0 = pn0;
        pg1 = pn1;
    }

    // head GEMV: out[b][n] = hT . W_head[n] + b_head[n]
    const float* hf = hs[S_ & 1];
    for (int n = t; n < N_; n += 128) {
        const float4* wr = (const float4*)(W_head + (size_t)n * H_);
        float acc = b_head[n];
#pragma unroll
        for (int q = 0; q < 16; q++) {
            float4 v = wr[q];
            acc = fmaf(v.x, hf[q * 4],     acc);
            acc = fmaf(v.y, hf[q * 4 + 1], acc);
            acc = fmaf(v.z, hf[q * 4 + 2], acc);
            acc = fmaf(v.w, hf[q * 4 + 3], acc);
        }
        outp[b * N_ + n] = acc;
    }
}

// ---------------------------------------------------------------------------
extern "C" void kernel_launch(void* const* d_in, const int* in_sizes, int n_in,
                              void* d_out, int out_size)
{
    const float* x       = (const float*)d_in[0];
    const int*   ei      = (const int*)  d_in[1];
    const float* w_lin   = (const float*)d_in[2];
    const float* att_src = (const float*)d_in[3];
    const float* att_dst = (const float*)d_in[4];
    const float* gbias   = (const float*)d_in[5];
    const float* W_ih    = (const float*)d_in[6];
    const float* W_hh    = (const float*)d_in[7];
    const float* b_ih    = (const float*)d_in[8];
    const float* b_hh    = (const float*)d_in[9];
    const float* W_head  = (const float*)d_in[10];
    const float* b_head  = (const float*)d_in[11];
    float*       out     = (float*)d_out;
    const int    E       = in_sizes[1] / 2;

    static int smem_set = 0;
    if (!smem_set) {
        cudaFuncSetAttribute(gemm_k, cudaFuncAttributeMaxDynamicSharedMemorySize,
                             SMEM_TOT);
        smem_set = 1;
    }

    zero_cnt_k<<<8, 256>>>();
    hist_k<<<(E + 255) / 256, 256>>>(ei, E);
    scan_k<<<1, 512>>>(E);
    scat_k<<<(E + 255) / 256, 256>>>(ei, E);
    gat_k<<<BS_ / 2, 256>>>(x, w_lin, att_src, att_dst);
    gemm_k<<<dim3(KSPLIT, NSPL), 256, SMEM_TOT>>>(W_ih, w_lin, gbias);
    reduce_k<<<(BS_ * G4_) / 256, 256>>>();
    lstm_k<<<B_, 128>>>(W_hh, b_ih, b_hh, W_head, b_head, out);
}

// round 14
// speedup vs baseline: 3.3071x; 1.1502x over previous
#include <cuda_runtime.h>
#include <cuda_fp16.h>
#include <cstdint>

// ---------------------------------------------------------------------------
#define B_   8
#define S_   32
#define N_   2000
#define GH_  32
#define H_   64
#define D_   64000          // N_*GH_
#define BS_  256
#define G4_  256

#define KSPLIT 74           // K-splits (each ~13.5 chunks of 64 over D_)
#define NSPL   2            // gate halves (128 each)
#define NCHUNK 1000         // D_/64
#define NST    28           // staged agg nodes per CTA (2 per chunk, max 14 chunks)

__device__ float g_agg[BS_ * N_];                    // 2 MB
__device__ float g_pg[BS_ * G4_];                    // 256 KB pre-gates
__device__ float g_part[KSPLIT * BS_ * G4_];         // 19.4 MB GEMM partials
// CSR scratch (edge list sorted by dst, rebuilt every call).
// g_cnt is left ZEROED by scan_k each call, so hist_k can start immediately.
__device__ int   g_cnt[N_];
__device__ int   g_off[N_ + 1];
__device__ int   g_cur[N_];
__device__ int   g_src[131072];

// ---------------------------------------------------------------------------
// helpers
// ---------------------------------------------------------------------------
__device__ __forceinline__ uint32_t smem_u32(const void* p) {
    uint32_t a;
    asm("{ .reg .u64 t; cvta.to.shared.u64 t, %1; cvt.u32.u64 %0, t; }"
        : "=r"(a) : "l"(p));
    return a;
}
#define SWZ(o) ((o) ^ (((o) >> 3) & 0x70))

__device__ __forceinline__ void ldsm4(uint32_t* r, uint32_t addr) {
    asm volatile("ldmatrix.sync.aligned.m8n8.x4.shared.b16 {%0,%1,%2,%3}, [%4];"
                 : "=r"(r[0]), "=r"(r[1]), "=r"(r[2]), "=r"(r[3]) : "r"(addr));
}
__device__ __forceinline__ void mma16816(float* c, const uint32_t* a,
                                         const uint32_t* b) {
    asm volatile(
        "mma.sync.aligned.m16n8k16.row.col.f32.f16.f16.f32 "
        "{%0,%1,%2,%3}, {%4,%5,%6,%7}, {%8,%9}, {%0,%1,%2,%3};"
        : "+f"(c[0]), "+f"(c[1]), "+f"(c[2]), "+f"(c[3])
        : "r"(a[0]), "r"(a[1]), "r"(a[2]), "r"(a[3]), "r"(b[0]), "r"(b[1]));
}
__device__ __forceinline__ float sigm_f(float v) {
    return __fdividef(1.f, 1.f + __expf(-v));
}
__device__ __forceinline__ float tanh_f(float v) {
    return 1.f - __fdividef(2.f, __expf(2.f * v) + 1.f);
}

// ---------------------------------------------------------------------------
// CSR build: histogram(dst) -> scan (re-zeros counts) -> scatter(src)
// ---------------------------------------------------------------------------
__global__ void hist_k(const int* __restrict__ ei, int E) {
    int t = blockIdx.x * 256 + threadIdx.x;
    if (t < E) atomicAdd(&g_cnt[ei[E + t]], 1);
}
__global__ __launch_bounds__(512) void scan_k(int E) {
    __shared__ int wsum[16];
    const int t = threadIdx.x, lane = t & 31, wid = t >> 5;
    int v[4];
    const int base = t * 4;
#pragma unroll
    for (int j = 0; j < 4; j++)
        v[j] = (base + j < N_) ? g_cnt[base + j] : 0;
    // re-zero counts for the NEXT call (deterministic: every call leaves 0)
#pragma unroll
    for (int j = 0; j < 4; j++)
        if (base + j < N_) g_cnt[base + j] = 0;
    int s = v[0] + v[1] + v[2] + v[3];
    int ps = s;
#pragma unroll
    for (int d = 1; d < 32; d <<= 1) {
        int o = __shfl_up_sync(0xFFFFFFFFu, ps, d);
        if (lane >= d) ps += o;
    }
    if (lane == 31) wsum[wid] = ps;
    __syncthreads();
    if (t < 16) {
        int w = wsum[t];
#pragma unroll
        for (int d = 1; d < 16; d <<= 1) {
            int o = __shfl_up_sync(0x0000FFFFu, w, d);
            if (t >= d) w += o;
        }
        wsum[t] = w;
    }
    __syncthreads();
    int run = ((wid > 0) ? wsum[wid - 1] : 0) + ps - s;
#pragma unroll
    for (int j = 0; j < 4; j++) {
        if (base + j < N_) {
            g_off[base + j] = run;
            g_cur[base + j] = run;
            run += v[j];
        }
    }
    if (t == 511) g_off[N_] = E;
}
__global__ void scat_k(const int* __restrict__ ei, int E) {
    int t = blockIdx.x * 256 + threadIdx.x;
    if (t < E) {
        int d = ei[E + t];
        int pos = atomicAdd(&g_cur[d], 1);
        g_src[pos] = ei[t];
    }
}

// ---------------------------------------------------------------------------
// Kernel 1: GAT gather — no atomics, no per-edge expf (factored exponential).
// ---------------------------------------------------------------------------
__global__ __launch_bounds__(256) void gat_k(
    const float* __restrict__ x, const float* __restrict__ w_lin,
    const float* __restrict__ att_src, const float* __restrict__ att_dst)
{
    __shared__ float xs[2][N_];
    __shared__ float ue[2][2][N_];

    const int bs0 = blockIdx.x * 2;
    const int tid = threadIdx.x;

    float cs = 0.f, cd = 0.f;
    for (int g = 0; g < GH_; g++) {
        float w = w_lin[g];
        cs = fmaf(w, att_src[g], cs);
        cd = fmaf(w, att_dst[g], cd);
    }
    for (int n = tid; n < N_; n += 256) {
        float x0 = x[(size_t)bs0 * N_ + n];
        float x1 = x[(size_t)(bs0 + 1) * N_ + n];
        xs[0][n] = x0;
        xs[1][n] = x1;
        ue[0][0][n] = __expf(cs * x0);
        ue[0][1][n] = __expf(0.2f * cs * x0);
        ue[1][0][n] = __expf(cs * x1);
        ue[1][1][n] = __expf(0.2f * cs * x1);
    }
    __syncthreads();

    for (int n = tid; n < N_; n += 256) {
        const int off = g_off[n], end = g_off[n + 1];
        const float x0d = xs[0][n], x1d = xs[1][n];
        const float cz0 = cd * x0d, cz1 = cd * x1d;
        const float vd0 = __expf(cz0),        vd1 = __expf(cz1);
        const float vq0 = __expf(0.2f * cz0), vq1 = __expf(0.2f * cz1);

        float z0 = cs * x0d + cz0;
        float z1 = cs * x1d + cz1;
        float w0 = (z0 > 0.f) ? ue[0][0][n] * vd0 : ue[0][1][n] * vq0;
        float w1 = (z1 > 0.f) ? ue[1][0][n] * vd1 : ue[1][1][n] * vq1;
        float den0 = w0, num0 = w0 * x0d;
        float den1 = w1, num1 = w1 * x1d;

        for (int p = off; p < end; p++) {
            int s = g_src[p];
            float x0s = xs[0][s];
            float x1s = xs[1][s];
            float za = cs * x0s + cz0;
            float zb = cs * x1s + cz1;
            float wa = (za > 0.f) ? ue[0][0][s] * vd0 : ue[0][1][s] * vq0;
            float wb = (zb > 0.f) ? ue[1][0][s] * vd1 : ue[1][1][s] * vq1;
            den0 += wa; num0 = fmaf(wa, x0s, num0);
            den1 += wb; num1 = fmaf(wb, x1s, num1);
        }
        g_agg[(size_t)bs0 * N_ + n]       = __fdividef(num0, den0);
        g_agg[(size_t)(bs0 + 1) * N_ + n] = __fdividef(num1, den1);
    }
}

// ---------------------------------------------------------------------------
// Kernel 2: fp16 2-term GEMM via mma.sync, double-buffered smem.
//   A split hi/lo fp16 (exact in A); W single fp16. Error = x*(w - wh) ~7e-5.
//   grid (74 K-splits, 2 gate-halves). CTA tile 256x128, warp tile 64x64.
//   2 mma terms share the same B fragments.
// ---------------------------------------------------------------------------
#define OFF_WL   0
#define OFF_GB   128
#define OFF_AGG  256                       // 256*28*4 = 28672 -> ends 28928
#define OFF_A0H  28928                     // 256x64 fp16 = 32768
#define OFF_A0L  61696
#define OFF_B0H  94464                     // 128x64 fp16 = 16384
#define OFF_A1H  110848
#define OFF_A1L  143616
#define OFF_B1H  176384
#define SMEM_TOT 192768

__device__ __forceinline__ void conv_tiles(
    char* sm, uint32_t oAH, uint32_t oAL, uint32_t oBH,
    const float* wl, const float* gb, const float* ag,
    const float* __restrict__ W_ih, int nh, int c, int cl2, int tid)
{
    // A tile (256x64 fp16 hi/lo) generated from agg
#pragma unroll
    for (int i = 0; i < 16; i++) {
        int idx = tid + i * 256;
        int row = idx >> 4, c4 = idx & 15;
        float a  = ag[row * NST + cl2 + (c4 >> 3)];
        int   g0 = (c4 & 7) * 4;
        __half hi[4], lo[4];
#pragma unroll
        for (int j = 0; j < 4; j++) {
            float v = fmaxf(fmaf(a, wl[g0 + j], gb[g0 + j]), 0.f);
            hi[j] = __float2half_rn(v);
            lo[j] = __float2half_rn(v - __half2float(hi[j]));
        }
        uint32_t off = SWZ((uint32_t)(row * 128 + c4 * 8));
        *(uint2*)(sm + oAH + off) = *(uint2*)hi;
        *(uint2*)(sm + oAL + off) = *(uint2*)lo;
    }
    // B tile (128x64 fp16) from W_ih
#pragma unroll
    for (int i = 0; i < 8; i++) {
        int idx = tid + i * 256;
        int row = idx >> 4, c4 = idx & 15;
        float4 w = *(const float4*)(W_ih + (size_t)(nh * 128 + row) * D_ +
                                    c * 64 + c4 * 4);
        __half hi[4];
        hi[0] = __float2half_rn(w.x);
        hi[1] = __float2half_rn(w.y);
        hi[2] = __float2half_rn(w.z);
        hi[3] = __float2half_rn(w.w);
        uint32_t off = SWZ((uint32_t)(row * 128 + c4 * 8));
        *(uint2*)(sm + oBH + off) = *(uint2*)hi;
    }
}

__global__ __launch_bounds__(256) void gemm_k(
    const float* __restrict__ W_ih,
    const float* __restrict__ w_lin_g, const float* __restrict__ gbias_g)
{
    extern __shared__ __align__(128) char sm[];
    const uint32_t sb = smem_u32(sm);
    const int tid  = threadIdx.x;
    const int lane = tid & 31;
    const int wid  = tid >> 5;
    const int z    = blockIdx.x;           // K split
    const int nh   = blockIdx.y;           // gate half
    const int c0   = z * NCHUNK / KSPLIT;
    const int c1   = (z + 1) * NCHUNK / KSPLIT;
    const int n0   = c0 * 2;

    if (tid < 32) {
        ((float*)(sm + OFF_WL))[tid] = w_lin_g[tid];
        ((float*)(sm + OFF_GB))[tid] = gbias_g[tid];
    }
    for (int i = tid; i < 256 * NST; i += 256) {
        int row = i / NST, nl = i % NST;
        ((float*)(sm + OFF_AGG))[i] = g_agg[(size_t)row * N_ + n0 + nl];
    }
    __syncthreads();

    const float* wl = (const float*)(sm + OFF_WL);
    const float* gb = (const float*)(sm + OFF_GB);
    const float* ag = (const float*)(sm + OFF_AGG);

    const uint32_t AH[2] = {OFF_A0H, OFF_A1H};
    const uint32_t AL[2] = {OFF_A0L, OFF_A1L};
    const uint32_t BH[2] = {OFF_B0H, OFF_B1H};

    const int mw = (wid & 3) * 64;
    const int nw = (wid >> 2) * 64;

    const uint32_t rowA = (uint32_t)(mw + (lane & 15)) * 128u;
    const uint32_t khA  = (uint32_t)(lane >> 4);
    const uint32_t swA  = (uint32_t)(lane & 7);
    const uint32_t rowB = (uint32_t)(nw + (lane & 7) + ((lane >> 4) << 3)) * 128u;
    const uint32_t khB  = (uint32_t)((lane >> 3) & 1);
    const uint32_t swB  = (uint32_t)(lane & 7);

    float acc[4][8][4];
#pragma unroll
    for (int mt = 0; mt < 4; mt++)
#pragma unroll
        for (int nt = 0; nt < 8; nt++)
#pragma unroll
            for (int q = 0; q < 4; q++) acc[mt][nt][q] = 0.f;

    conv_tiles(sm, AH[0], AL[0], BH[0], wl, gb, ag, W_ih, nh, c0, 0, tid);
    __syncthreads();

    for (int c = c0; c < c1; c++) {
        const int st = (c - c0) & 1;
        if (c + 1 < c1)
            conv_tiles(sm, AH[st ^ 1], AL[st ^ 1], BH[st ^ 1],
                       wl, gb, ag, W_ih, nh, c + 1, (c + 1 - c0) * 2, tid);

        const uint32_t bAH = sb + AH[st], bAL = sb + AL[st];
        const uint32_t bBH = sb + BH[st];
#pragma unroll
        for (int ks = 0; ks < 4; ks++) {
            uint32_t af[4][4], al[4][4], bh[4][4];
            const uint32_t cA = (((uint32_t)(ks * 2) + khA) ^ swA) << 4;
            const uint32_t cB = (((uint32_t)(ks * 2) + khB) ^ swB) << 4;
#pragma unroll
            for (int np = 0; np < 4; np++)
                ldsm4(bh[np], bBH + rowB + np * 2048 + cB);
#pragma unroll
            for (int mt = 0; mt < 4; mt++)
                ldsm4(af[mt], bAH + rowA + mt * 2048 + cA);
#pragma unroll
            for (int mt = 0; mt < 4; mt++)
#pragma unroll
                for (int nt = 0; nt < 8; nt++)
                    mma16816(acc[mt][nt], af[mt], &bh[nt >> 1][(nt & 1) * 2]);
#pragma unroll
            for (int mt = 0; mt < 4; mt++)
                ldsm4(al[mt], bAL + rowA + mt * 2048 + cA);
#pragma unroll
            for (int mt = 0; mt < 4; mt++)
#pragma unroll
                for (int nt = 0; nt < 8; nt++)
                    mma16816(acc[mt][nt], al[mt], &bh[nt >> 1][(nt & 1) * 2]);
        }
        __syncthreads();
    }

    const int gq = lane >> 2;
    const int t2 = (lane & 3) * 2;
    float* base = g_part + (size_t)z * (BS_ * G4_);
#pragma unroll
    for (int mt = 0; mt < 4; mt++)
#pragma unroll
        for (int nt = 0; nt < 8; nt++) {
            int row = mw + mt * 16 + gq;
            int col = nh * 128 + nw + nt * 8 + t2;
            *(float2*)(base + (size_t)row * G4_ + col) =
                make_float2(acc[mt][nt][0], acc[mt][nt][1]);
            *(float2*)(base + (size_t)(row + 8) * G4_ + col) =
                make_float2(acc[mt][nt][2], acc[mt][nt][3]);
        }
}

// ---------------------------------------------------------------------------
// Kernel 2b: reduce K-split partials into g_pg
// ---------------------------------------------------------------------------
__global__ __launch_bounds__(256) void reduce_k() {
    const int i = blockIdx.x * 256 + threadIdx.x;
    float s0 = 0.f, s1 = 0.f, s2 = 0.f, s3 = 0.f;
#pragma unroll
    for (int zz = 0; zz < 72; zz += 4) {
        s0 += g_part[(size_t)(zz + 0) * 65536 + i];
        s1 += g_part[(size_t)(zz + 1) * 65536 + i];
        s2 += g_part[(size_t)(zz + 2) * 65536 + i];
        s3 += g_part[(size_t)(zz + 3) * 65536 + i];
    }
    s0 += g_part[(size_t)72 * 65536 + i];
    s1 += g_part[(size_t)73 * 65536 + i];
    g_pg[i] = (s0 + s1) + (s2 + s3);
}

// ---------------------------------------------------------------------------
// Kernel 3: LSTM recurrence (pairs, W_hh in regs, 1 sync/step) + head GEMV
// ---------------------------------------------------------------------------
__global__ __launch_bounds__(128) void lstm_k(
    const float* __restrict__ W_hh, const float* __restrict__ b_ih,
    const float* __restrict__ b_hh, const float* __restrict__ W_head,
    const float* __restrict__ b_head, float* __restrict__ outp)
{
    __shared__ __align__(16) float hs[2][H_];

    const int t = threadIdx.x, b = blockIdx.x;
    const int j = t >> 1, p = t & 1;
    const int r0 = (p == 0) ? j          : H_ + j;      // i | f
    const int r1 = (p == 0) ? 2 * H_ + j : 3 * H_ + j;  // g | o

    float w0[H_], w1[H_];
#pragma unroll
    for (int k = 0; k < H_; k++) {
        w0[k] = W_hh[r0 * H_ + k];
        w1[k] = W_hh[r1 * H_ + k];
    }
    const float bias0 = b_ih[r0] + b_hh[r0];
    const float bias1 = b_ih[r1] + b_hh[r1];
    float cval = 0.f;
    if (p == 1) hs[0][j] = 0.f;
    float pg0 = g_pg[(b * S_) * G4_ + r0];
    float pg1 = g_pg[(b * S_) * G4_ + r1];
    __syncthreads();

    for (int s = 0; s < S_; s++) {
        float pn0 = 0.f, pn1 = 0.f;
        if (s + 1 < S_) {
            pn0 = g_pg[(b * S_ + s + 1) * G4_ + r0];
            pn1 = g_pg[(b * S_ + s + 1) * G4_ + r1];
        }
        const float4* h4 = (const float4*)(hs[s & 1]);
        float a0 = 0.f, a1 = 0.f, a2 = 0.f, a3 = 0.f;
        float d0 = 0.f, d1 = 0.f, d2 = 0.f, d3 = 0.f;
#pragma unroll
        for (int k = 0; k < 16; k++) {
            float4 hv = h4[k];
            a0 = fmaf(w0[4 * k],     hv.x, a0);
            a1 = fmaf(w0[4 * k + 1], hv.y, a1);
            a2 = fmaf(w0[4 * k + 2], hv.z, a2);
            a3 = fmaf(w0[4 * k + 3], hv.w, a3);
            d0 = fmaf(w1[4 * k],     hv.x, d0);
            d1 = fmaf(w1[4 * k + 1], hv.y, d1);
            d2 = fmaf(w1[4 * k + 2], hv.z, d2);
            d3 = fmaf(w1[4 * k + 3], hv.w, d3);
        }
        float g0 = (a0 + a1) + (a2 + a3) + pg0 + bias0;
        float g1 = (d0 + d1) + (d2 + d3) + pg1 + bias1;

        float s0 = sigm_f(g0);
        float s1 = (p == 0) ? tanh_f(g1) : sigm_f(g1);
        float prod  = s0 * s1;
        float other = __shfl_xor_sync(0xFFFFFFFFu, prod, 1);
        if (p == 1) {
            cval = fmaf(s0, cval, other);
            hs[(s + 1) & 1][j] = s1 * tanh_f(cval);
        }
        __syncthreads();
        pg0 = pn0;
        pg1 = pn1;
    }

    const float* hf = hs[S_ & 1];
    for (int n = t; n < N_; n += 128) {
        const float4* wr = (const float4*)(W_head + (size_t)n * H_);
        float acc = b_head[n];
#pragma unroll
        for (int q = 0; q < 16; q++) {
            float4 v = wr[q];
            acc = fmaf(v.x, hf[q * 4],     acc);
            acc = fmaf(v.y, hf[q * 4 + 1], acc);
            acc = fmaf(v.z, hf[q * 4 + 2], acc);
            acc = fmaf(v.w, hf[q * 4 + 3], acc);
        }
        outp[b * N_ + n] = acc;
    }
}

// ---------------------------------------------------------------------------
extern "C" void kernel_launch(void* const* d_in, const int* in_sizes, int n_in,
                              void* d_out, int out_size)
{
    const float* x       = (const float*)d_in[0];
    const int*   ei      = (const int*)  d_in[1];
    const float* w_lin   = (const float*)d_in[2];
    const float* att_src = (const float*)d_in[3];
    const float* att_dst = (const float*)d_in[4];
    const float* gbias   = (const float*)d_in[5];
    const float* W_ih    = (const float*)d_in[6];
    const float* W_hh    = (const float*)d_in[7];
    const float* b_ih    = (const float*)d_in[8];
    const float* b_hh    = (const float*)d_in[9];
    const float* W_head  = (const float*)d_in[10];
    const float* b_head  = (const float*)d_in[11];
    float*       out     = (float*)d_out;
    const int    E       = in_sizes[1] / 2;

    static int smem_set = 0;
    if (!smem_set) {
        cudaFuncSetAttribute(gemm_k, cudaFuncAttributeMaxDynamicSharedMemorySize,
                             SMEM_TOT);
        smem_set = 1;
    }

    hist_k<<<(E + 255) / 256, 256>>>(ei, E);
    scan_k<<<1, 512>>>(E);
    scat_k<<<(E + 255) / 256, 256>>>(ei, E);
    gat_k<<<BS_ / 2, 256>>>(x, w_lin, att_src, att_dst);
    gemm_k<<<dim3(KSPLIT, NSPL), 256, SMEM_TOT>>>(W_ih, w_lin, gbias);
    reduce_k<<<(BS_ * G4_) / 256, 256>>>();
    lstm_k<<<B_, 128>>>(W_hh, b_ih, b_hh, W_head, b_head, out);
}

// round 15
// speedup vs baseline: 3.5897x; 1.0855x over previous
#include <cuda_runtime.h>
#include <cuda_fp16.h>
#include <cstdint>

// ---------------------------------------------------------------------------
#define B_   8
#define S_   32
#define N_   2000
#define GH_  32
#define H_   64
#define D_   64000          // N_*GH_
#define BS_  256
#define G4_  256

#define KSPLIT 74           // K-splits (each ~13.5 chunks of 64 over D_)
#define NSPL   2            // gate halves (128 each)
#define NCHUNK 1000         // D_/64
#define NST    28           // staged agg nodes per CTA (2 per chunk, max 14 chunks)

__device__ float g_agg[BS_ * N_];                    // 2 MB
__device__ float g_pg[BS_ * G4_];                    // 256 KB pre-gates
__device__ float g_part[KSPLIT * BS_ * G4_];         // 19.4 MB GEMM partials
// CSR scratch (edge list sorted by dst, rebuilt every call).
// g_cnt is left ZEROED by scan_k each call, so hist_k can start immediately.
__device__ int   g_cnt[N_];
__device__ int   g_off[N_ + 1];
__device__ int   g_cur[N_];
__device__ int   g_src[131072];

// ---------------------------------------------------------------------------
// helpers
// ---------------------------------------------------------------------------
__device__ __forceinline__ uint32_t smem_u32(const void* p) {
    uint32_t a;
    asm("{ .reg .u64 t; cvta.to.shared.u64 t, %1; cvt.u32.u64 %0, t; }"
        : "=r"(a) : "l"(p));
    return a;
}
#define SWZ(o) ((o) ^ (((o) >> 3) & 0x70))

__device__ __forceinline__ void ldsm4(uint32_t* r, uint32_t addr) {
    asm volatile("ldmatrix.sync.aligned.m8n8.x4.shared.b16 {%0,%1,%2,%3}, [%4];"
                 : "=r"(r[0]), "=r"(r[1]), "=r"(r[2]), "=r"(r[3]) : "r"(addr));
}
__device__ __forceinline__ void mma16816(float* c, const uint32_t* a,
                                         const uint32_t* b) {
    asm volatile(
        "mma.sync.aligned.m16n8k16.row.col.f32.f16.f16.f32 "
        "{%0,%1,%2,%3}, {%4,%5,%6,%7}, {%8,%9}, {%0,%1,%2,%3};"
        : "+f"(c[0]), "+f"(c[1]), "+f"(c[2]), "+f"(c[3])
        : "r"(a[0]), "r"(a[1]), "r"(a[2]), "r"(a[3]), "r"(b[0]), "r"(b[1]));
}
__device__ __forceinline__ float sigm_f(float v) {
    return __fdividef(1.f, 1.f + __expf(-v));
}
__device__ __forceinline__ float tanh_f(float v) {
    return 1.f - __fdividef(2.f, __expf(2.f * v) + 1.f);
}

// ---------------------------------------------------------------------------
// CSR build: histogram(dst) -> scan (re-zeros counts) -> scatter(src)
// ---------------------------------------------------------------------------
__global__ void hist_k(const int* __restrict__ ei, int E) {
    int t = blockIdx.x * 256 + threadIdx.x;
    if (t < E) atomicAdd(&g_cnt[ei[E + t]], 1);
}
__global__ __launch_bounds__(512) void scan_k(int E) {
    __shared__ int wsum[16];
    const int t = threadIdx.x, lane = t & 31, wid = t >> 5;
    int v[4];
    const int base = t * 4;
#pragma unroll
    for (int j = 0; j < 4; j++)
        v[j] = (base + j < N_) ? g_cnt[base + j] : 0;
#pragma unroll
    for (int j = 0; j < 4; j++)
        if (base + j < N_) g_cnt[base + j] = 0;
    int s = v[0] + v[1] + v[2] + v[3];
    int ps = s;
#pragma unroll
    for (int d = 1; d < 32; d <<= 1) {
        int o = __shfl_up_sync(0xFFFFFFFFu, ps, d);
        if (lane >= d) ps += o;
    }
    if (lane == 31) wsum[wid] = ps;
    __syncthreads();
    if (t < 16) {
        int w = wsum[t];
#pragma unroll
        for (int d = 1; d < 16; d <<= 1) {
            int o = __shfl_up_sync(0x0000FFFFu, w, d);
            if (t >= d) w += o;
        }
        wsum[t] = w;
    }
    __syncthreads();
    int run = ((wid > 0) ? wsum[wid - 1] : 0) + ps - s;
#pragma unroll
    for (int j = 0; j < 4; j++) {
        if (base + j < N_) {
            g_off[base + j] = run;
            g_cur[base + j] = run;
            run += v[j];
        }
    }
    if (t == 511) g_off[N_] = E;
}
__global__ void scat_k(const int* __restrict__ ei, int E) {
    int t = blockIdx.x * 256 + threadIdx.x;
    if (t < E) {
        int d = ei[E + t];
        int pos = atomicAdd(&g_cur[d], 1);
        g_src[pos] = ei[t];
    }
}

// ---------------------------------------------------------------------------
// Kernel 1: GAT gather — ONE bs row per CTA (grid 256: full-chip coverage,
//   occupancy was the round-14 bottleneck). Factored exponential, no atomics.
// ---------------------------------------------------------------------------
__global__ __launch_bounds__(256) void gat_k(
    const float* __restrict__ x, const float* __restrict__ w_lin,
    const float* __restrict__ att_src, const float* __restrict__ att_dst)
{
    __shared__ float xs[N_];
    __shared__ float up[N_];
    __shared__ float un[N_];

    const int bs  = blockIdx.x;
    const int tid = threadIdx.x;

    float cs = 0.f, cd = 0.f;
    for (int g = 0; g < GH_; g++) {
        float w = w_lin[g];
        cs = fmaf(w, att_src[g], cs);
        cd = fmaf(w, att_dst[g], cd);
    }
    for (int n = tid; n < N_; n += 256) {
        float xv = x[(size_t)bs * N_ + n];
        xs[n] = xv;
        up[n] = __expf(cs * xv);
        un[n] = __expf(0.2f * cs * xv);
    }
    __syncthreads();

    for (int n = tid; n < N_; n += 256) {
        const int off = g_off[n], end = g_off[n + 1];
        const float xd = xs[n];
        const float cz = cd * xd;
        const float vd = __expf(cz);
        const float vq = __expf(0.2f * cz);

        // self loop
        float z0 = cs * xd + cz;
        float w0 = (z0 > 0.f) ? up[n] * vd : un[n] * vq;
        float den = w0, num = w0 * xd;

        for (int p = off; p < end; p++) {
            int s = g_src[p];
            float xv = xs[s];
            float za = cs * xv + cz;
            float wa = (za > 0.f) ? up[s] * vd : un[s] * vq;
            den += wa;
            num = fmaf(wa, xv, num);
        }
        g_agg[(size_t)bs * N_ + n] = __fdividef(num, den);
    }
}

// ---------------------------------------------------------------------------
// Kernel 2: fp16 1-TERM GEMM via mma.sync, double-buffered smem.
//   A fp16 (computed fp32, rounded once); W fp16. Error ~3e-4 << 1e-3.
//   grid (74 K-splits, 2 gate-halves). CTA tile 256x128, warp tile 64x64.
// ---------------------------------------------------------------------------
#define OFF_WL   0
#define OFF_GB   128
#define OFF_AGG  256                       // 256*28*4 = 28672 -> ends 28928
#define OFF_A0   28928                     // 256x64 fp16 = 32768
#define OFF_B0   61696                     // 128x64 fp16 = 16384
#define OFF_A1   78080
#define OFF_B1   110848
#define SMEM_TOT 127232

__device__ __forceinline__ void conv_tiles(
    char* sm, uint32_t oA, uint32_t oB,
    const float* wl, const float* gb, const float* ag,
    const float* __restrict__ W_ih, int nh, int c, int cl2, int tid)
{
    // A tile (256x64 fp16) generated from agg
#pragma unroll
    for (int i = 0; i < 16; i++) {
        int idx = tid + i * 256;
        int row = idx >> 4, c4 = idx & 15;
        float a  = ag[row * NST + cl2 + (c4 >> 3)];
        int   g0 = (c4 & 7) * 4;
        __half hv[4];
#pragma unroll
        for (int j = 0; j < 4; j++) {
            float v = fmaxf(fmaf(a, wl[g0 + j], gb[g0 + j]), 0.f);
            hv[j] = __float2half_rn(v);
        }
        uint32_t off = SWZ((uint32_t)(row * 128 + c4 * 8));
        *(uint2*)(sm + oA + off) = *(uint2*)hv;
    }
    // B tile (128x64 fp16) from W_ih
#pragma unroll
    for (int i = 0; i < 8; i++) {
        int idx = tid + i * 256;
        int row = idx >> 4, c4 = idx & 15;
        float4 w = *(const float4*)(W_ih + (size_t)(nh * 128 + row) * D_ +
                                    c * 64 + c4 * 4);
        __half hv[4];
        hv[0] = __float2half_rn(w.x);
        hv[1] = __float2half_rn(w.y);
        hv[2] = __float2half_rn(w.z);
        hv[3] = __float2half_rn(w.w);
        uint32_t off = SWZ((uint32_t)(row * 128 + c4 * 8));
        *(uint2*)(sm + oB + off) = *(uint2*)hv;
    }
}

__global__ __launch_bounds__(256) void gemm_k(
    const float* __restrict__ W_ih,
    const float* __restrict__ w_lin_g, const float* __restrict__ gbias_g)
{
    extern __shared__ __align__(128) char sm[];
    const uint32_t sb = smem_u32(sm);
    const int tid  = threadIdx.x;
    const int lane = tid & 31;
    const int wid  = tid >> 5;
    const int z    = blockIdx.x;           // K split
    const int nh   = blockIdx.y;           // gate half
    const int c0   = z * NCHUNK / KSPLIT;
    const int c1   = (z + 1) * NCHUNK / KSPLIT;
    const int n0   = c0 * 2;

    if (tid < 32) {
        ((float*)(sm + OFF_WL))[tid] = w_lin_g[tid];
        ((float*)(sm + OFF_GB))[tid] = gbias_g[tid];
    }
    for (int i = tid; i < 256 * NST; i += 256) {
        int row = i / NST, nl = i % NST;
        ((float*)(sm + OFF_AGG))[i] = g_agg[(size_t)row * N_ + n0 + nl];
    }
    __syncthreads();

    const float* wl = (const float*)(sm + OFF_WL);
    const float* gb = (const float*)(sm + OFF_GB);
    const float* ag = (const float*)(sm + OFF_AGG);

    const uint32_t AB[2] = {OFF_A0, OFF_A1};
    const uint32_t BB[2] = {OFF_B0, OFF_B1};

    const int mw = (wid & 3) * 64;
    const int nw = (wid >> 2) * 64;

    const uint32_t rowA = (uint32_t)(mw + (lane & 15)) * 128u;
    const uint32_t khA  = (uint32_t)(lane >> 4);
    const uint32_t swA  = (uint32_t)(lane & 7);
    const uint32_t rowB = (uint32_t)(nw + (lane & 7) + ((lane >> 4) << 3)) * 128u;
    const uint32_t khB  = (uint32_t)((lane >> 3) & 1);
    const uint32_t swB  = (uint32_t)(lane & 7);

    float acc[4][8][4];
#pragma unroll
    for (int mt = 0; mt < 4; mt++)
#pragma unroll
        for (int nt = 0; nt < 8; nt++)
#pragma unroll
            for (int q = 0; q < 4; q++) acc[mt][nt][q] = 0.f;

    conv_tiles(sm, AB[0], BB[0], wl, gb, ag, W_ih, nh, c0, 0, tid);
    __syncthreads();

    for (int c = c0; c < c1; c++) {
        const int st = (c - c0) & 1;
        if (c + 1 < c1)
            conv_tiles(sm, AB[st ^ 1], BB[st ^ 1],
                       wl, gb, ag, W_ih, nh, c + 1, (c + 1 - c0) * 2, tid);

        const uint32_t bA = sb + AB[st];
        const uint32_t bB = sb + BB[st];
#pragma unroll
        for (int ks = 0; ks < 4; ks++) {
            uint32_t af[4][4], bh[4][4];
            const uint32_t cA = (((uint32_t)(ks * 2) + khA) ^ swA) << 4;
            const uint32_t cB = (((uint32_t)(ks * 2) + khB) ^ swB) << 4;
#pragma unroll
            for (int np = 0; np < 4; np++)
                ldsm4(bh[np], bB + rowB + np * 2048 + cB);
#pragma unroll
            for (int mt = 0; mt < 4; mt++)
                ldsm4(af[mt], bA + rowA + mt * 2048 + cA);
#pragma unroll
            for (int mt = 0; mt < 4; mt++)
#pragma unroll
                for (int nt = 0; nt < 8; nt++)
                    mma16816(acc[mt][nt], af[mt], &bh[nt >> 1][(nt & 1) * 2]);
        }
        __syncthreads();
    }

    const int gq = lane >> 2;
    const int t2 = (lane & 3) * 2;
    float* base = g_part + (size_t)z * (BS_ * G4_);
#pragma unroll
    for (int mt = 0; mt < 4; mt++)
#pragma unroll
        for (int nt = 0; nt < 8; nt++) {
            int row = mw + mt * 16 + gq;
            int col = nh * 128 + nw + nt * 8 + t2;
            *(float2*)(base + (size_t)row * G4_ + col) =
                make_float2(acc[mt][nt][0], acc[mt][nt][1]);
            *(float2*)(base + (size_t)(row + 8) * G4_ + col) =
                make_float2(acc[mt][nt][2], acc[mt][nt][3]);
        }
}

// ---------------------------------------------------------------------------
// Kernel 2b: reduce K-split partials into g_pg
// ---------------------------------------------------------------------------
__global__ __launch_bounds__(256) void reduce_k() {
    const int i = blockIdx.x * 256 + threadIdx.x;
    float s0 = 0.f, s1 = 0.f, s2 = 0.f, s3 = 0.f;
#pragma unroll
    for (int zz = 0; zz < 72; zz += 4) {
        s0 += g_part[(size_t)(zz + 0) * 65536 + i];
        s1 += g_part[(size_t)(zz + 1) * 65536 + i];
        s2 += g_part[(size_t)(zz + 2) * 65536 + i];
        s3 += g_part[(size_t)(zz + 3) * 65536 + i];
    }
    s0 += g_part[(size_t)72 * 65536 + i];
    s1 += g_part[(size_t)73 * 65536 + i];
    g_pg[i] = (s0 + s1) + (s2 + s3);
}

// ---------------------------------------------------------------------------
// Kernel 3: LSTM recurrence (pairs, W_hh in regs, 1 sync/step) + head GEMV
// ---------------------------------------------------------------------------
__global__ __launch_bounds__(128) void lstm_k(
    const float* __restrict__ W_hh, const float* __restrict__ b_ih,
    const float* __restrict__ b_hh, const float* __restrict__ W_head,
    const float* __restrict__ b_head, float* __restrict__ outp)
{
    __shared__ __align__(16) float hs[2][H_];

    const int t = threadIdx.x, b = blockIdx.x;
    const int j = t >> 1, p = t & 1;
    const int r0 = (p == 0) ? j          : H_ + j;      // i | f
    const int r1 = (p == 0) ? 2 * H_ + j : 3 * H_ + j;  // g | o

    float w0[H_], w1[H_];
#pragma unroll
    for (int k = 0; k < H_; k++) {
        w0[k] = W_hh[r0 * H_ + k];
        w1[k] = W_hh[r1 * H_ + k];
    }
    const float bias0 = b_ih[r0] + b_hh[r0];
    const float bias1 = b_ih[r1] + b_hh[r1];
    float cval = 0.f;
    if (p == 1) hs[0][j] = 0.f;
    float pg0 = g_pg[(b * S_) * G4_ + r0];
    float pg1 = g_pg[(b * S_) * G4_ + r1];
    __syncthreads();

    for (int s = 0; s < S_; s++) {
        float pn0 = 0.f, pn1 = 0.f;
        if (s + 1 < S_) {
            pn0 = g_pg[(b * S_ + s + 1) * G4_ + r0];
            pn1 = g_pg[(b * S_ + s + 1) * G4_ + r1];
        }
        const float4* h4 = (const float4*)(hs[s & 1]);
        float a0 = 0.f, a1 = 0.f, a2 = 0.f, a3 = 0.f;
        float d0 = 0.f, d1 = 0.f, d2 = 0.f, d3 = 0.f;
#pragma unroll
        for (int k = 0; k < 16; k++) {
            float4 hv = h4[k];
            a0 = fmaf(w0[4 * k],     hv.x, a0);
            a1 = fmaf(w0[4 * k + 1], hv.y, a1);
            a2 = fmaf(w0[4 * k + 2], hv.z, a2);
            a3 = fmaf(w0[4 * k + 3], hv.w, a3);
            d0 = fmaf(w1[4 * k],     hv.x, d0);
            d1 = fmaf(w1[4 * k + 1], hv.y, d1);
            d2 = fmaf(w1[4 * k + 2], hv.z, d2);
            d3 = fmaf(w1[4 * k + 3], hv.w, d3);
        }
        float g0 = (a0 + a1) + (a2 + a3) + pg0 + bias0;
        float g1 = (d0 + d1) + (d2 + d3) + pg1 + bias1;

        float s0 = sigm_f(g0);
        float s1 = (p == 0) ? tanh_f(g1) : sigm_f(g1);
        float prod  = s0 * s1;
        float other = __shfl_xor_sync(0xFFFFFFFFu, prod, 1);
        if (p == 1) {
            cval = fmaf(s0, cval, other);
            hs[(s + 1) & 1][j] = s1 * tanh_f(cval);
        }
        __syncthreads();
        pg0 = pn0;
        pg1 = pn1;
    }

    const float* hf = hs[S_ & 1];
    for (int n = t; n < N_; n += 128) {
        const float4* wr = (const float4*)(W_head + (size_t)n * H_);
        float acc = b_head[n];
#pragma unroll
        for (int q = 0; q < 16; q++) {
            float4 v = wr[q];
            acc = fmaf(v.x, hf[q * 4],     acc);
            acc = fmaf(v.y, hf[q * 4 + 1], acc);
            acc = fmaf(v.z, hf[q * 4 + 2], acc);
            acc = fmaf(v.w, hf[q * 4 + 3], acc);
        }
        outp[b * N_ + n] = acc;
    }
}

// ---------------------------------------------------------------------------
extern "C" void kernel_launch(void* const* d_in, const int* in_sizes, int n_in,
                              void* d_out, int out_size)
{
    const float* x       = (const float*)d_in[0];
    const int*   ei      = (const int*)  d_in[1];
    const float* w_lin   = (const float*)d_in[2];
    const float* att_src = (const float*)d_in[3];
    const float* att_dst = (const float*)d_in[4];
    const float* gbias   = (const float*)d_in[5];
    const float* W_ih    = (const float*)d_in[6];
    const float* W_hh    = (const float*)d_in[7];
    const float* b_ih    = (const float*)d_in[8];
    const float* b_hh    = (const float*)d_in[9];
    const float* W_head  = (const float*)d_in[10];
    const float* b_head  = (const float*)d_in[11];
    float*       out     = (float*)d_out;
    const int    E       = in_sizes[1] / 2;

    static int smem_set = 0;
    if (!smem_set) {
        cudaFuncSetAttribute(gemm_k, cudaFuncAttributeMaxDynamicSharedMemorySize,
                             SMEM_TOT);
        smem_set = 1;
    }

    hist_k<<<(E + 255) / 256, 256>>>(ei, E);
    scan_k<<<1, 512>>>(E);
    scat_k<<<(E + 255) / 256, 256>>>(ei, E);
    gat_k<<<BS_, 256>>>(x, w_lin, att_src, att_dst);
    gemm_k<<<dim3(KSPLIT, NSPL), 256, SMEM_TOT>>>(W_ih, w_lin, gbias);
    reduce_k<<<(BS_ * G4_) / 256, 256>>>();
    lstm_k<<<B_, 128>>>(W_hh, b_ih, b_hh, W_head, b_head, out);
}

// round 16
// speedup vs baseline: 3.8641x; 1.0764x over previous
#include <cuda_runtime.h>
#include <cuda_fp16.h>
#include <cstdint>

// ---------------------------------------------------------------------------
#define B_   8
#define S_   32
#define N_   2000
#define GH_  32
#define H_   64
#define D_   64000          // N_*GH_
#define BS_  256
#define G4_  256

#define KSPLIT 74           // K-splits (each 13-14 chunks of 64 over D_)
#define NSPL   2            // gate halves (128 each)
#define NCHUNK 1000         // D_/64

__device__ float  g_xt[N_ * BS_];                    // 2 MB   x transposed [n][bs]
__device__ float  g_aggt[N_ * BS_];                  // 2 MB   agg [n][bs]
__device__ float  g_pg[BS_ * G4_];                   // 256 KB pre-gates
__device__ float  g_part[KSPLIT * BS_ * G4_];        // 19.4 MB GEMM partials
__device__ __half g_wh[(size_t)G4_ * D_];            // 32 MB  W_ih in fp16
// CSR scratch (g_cnt left zeroed by scan_k each call)
__device__ int    g_cnt[N_];
__device__ int    g_off[N_ + 1];
__device__ int    g_cur[N_];
__device__ int    g_src[131072];

// ---------------------------------------------------------------------------
// helpers
// ---------------------------------------------------------------------------
__device__ __forceinline__ uint32_t smem_u32(const void* p) {
    uint32_t a;
    asm("{ .reg .u64 t; cvta.to.shared.u64 t, %1; cvt.u32.u64 %0, t; }"
        : "=r"(a) : "l"(p));
    return a;
}
#define SWZ(o) ((o) ^ (((o) >> 3) & 0x70))

__device__ __forceinline__ void ldsm4(uint32_t* r, uint32_t addr) {
    asm volatile("ldmatrix.sync.aligned.m8n8.x4.shared.b16 {%0,%1,%2,%3}, [%4];"
                 : "=r"(r[0]), "=r"(r[1]), "=r"(r[2]), "=r"(r[3]) : "r"(addr));
}
__device__ __forceinline__ void mma16816(float* c, const uint32_t* a,
                                         const uint32_t* b) {
    asm volatile(
        "mma.sync.aligned.m16n8k16.row.col.f32.f16.f16.f32 "
        "{%0,%1,%2,%3}, {%4,%5,%6,%7}, {%8,%9}, {%0,%1,%2,%3};"
        : "+f"(c[0]), "+f"(c[1]), "+f"(c[2]), "+f"(c[3])
        : "r"(a[0]), "r"(a[1]), "r"(a[2]), "r"(a[3]), "r"(b[0]), "r"(b[1]));
}
__device__ __forceinline__ void cp16(uint32_t dst, const void* src) {
    asm volatile("cp.async.cg.shared.global [%0], [%1], 16;"
                 :: "r"(dst), "l"(src));
}
#define CP_COMMIT() asm volatile("cp.async.commit_group;" ::: "memory")
#define CP_WAIT0()  asm volatile("cp.async.wait_group 0;"  ::: "memory")

__device__ __forceinline__ float sigm_f(float v) {
    return __fdividef(1.f, 1.f + __expf(-v));
}
__device__ __forceinline__ float tanh_f(float v) {
    return 1.f - __fdividef(2.f, __expf(2.f * v) + 1.f);
}

// ---------------------------------------------------------------------------
// CSR build: histogram(dst) -> scan (re-zeros counts) -> scatter(src)
// ---------------------------------------------------------------------------
__global__ void hist_k(const int* __restrict__ ei, int E) {
    int t = blockIdx.x * 256 + threadIdx.x;
    if (t < E) atomicAdd(&g_cnt[ei[E + t]], 1);
}
__global__ __launch_bounds__(512) void scan_k(int E) {
    __shared__ int wsum[16];
    const int t = threadIdx.x, lane = t & 31, wid = t >> 5;
    int v[4];
    const int base = t * 4;
#pragma unroll
    for (int j = 0; j < 4; j++)
        v[j] = (base + j < N_) ? g_cnt[base + j] : 0;
#pragma unroll
    for (int j = 0; j < 4; j++)
        if (base + j < N_) g_cnt[base + j] = 0;
    int s = v[0] + v[1] + v[2] + v[3];
    int ps = s;
#pragma unroll
    for (int d = 1; d < 32; d <<= 1) {
        int o = __shfl_up_sync(0xFFFFFFFFu, ps, d);
        if (lane >= d) ps += o;
    }
    if (lane == 31) wsum[wid] = ps;
    __syncthreads();
    if (t < 16) {
        int w = wsum[t];
#pragma unroll
        for (int d = 1; d < 16; d <<= 1) {
            int o = __shfl_up_sync(0x0000FFFFu, w, d);
            if (t >= d) w += o;
        }
        wsum[t] = w;
    }
    __syncthreads();
    int run = ((wid > 0) ? wsum[wid - 1] : 0) + ps - s;
#pragma unroll
    for (int j = 0; j < 4; j++) {
        if (base + j < N_) {
            g_off[base + j] = run;
            g_cur[base + j] = run;
            run += v[j];
        }
    }
    if (t == 511) g_off[N_] = E;
}
__global__ void scat_k(const int* __restrict__ ei, int E) {
    int t = blockIdx.x * 256 + threadIdx.x;
    if (t < E) {
        int d = ei[E + t];
        int pos = atomicAdd(&g_cur[d], 1);
        g_src[pos] = ei[t];
    }
}

// ---------------------------------------------------------------------------
// Kernel A: transpose x [BS][N] -> g_xt [N][BS] (32x32 smem tiles)
// ---------------------------------------------------------------------------
__global__ __launch_bounds__(256) void xpose_k(const float* __restrict__ x) {
    __shared__ float t[32][33];
    const int nb = blockIdx.x * 32, bb = blockIdx.y * 32;
    const int tx = threadIdx.x & 31, ty = threadIdx.x >> 5;
#pragma unroll
    for (int j = 0; j < 32; j += 8) {
        int col = nb + tx;
        if (col < N_) t[ty + j][tx] = x[(size_t)(bb + ty + j) * N_ + col];
    }
    __syncthreads();
#pragma unroll
    for (int j = 0; j < 32; j += 8) {
        int row = nb + ty + j;
        if (row < N_) g_xt[(size_t)row * BS_ + bb + tx] = t[tx][ty + j];
    }
}

// ---------------------------------------------------------------------------
// Kernel B: pre-convert W_ih to fp16 (one float4 -> 8B per thread)
// ---------------------------------------------------------------------------
__global__ __launch_bounds__(256) void wconv_k(const float* __restrict__ W) {
    size_t i = (size_t)blockIdx.x * 256 + threadIdx.x;
    float4 w = ((const float4*)W)[i];
    __half2 a = __floats2half2_rn(w.x, w.y);
    __half2 b = __floats2half2_rn(w.z, w.w);
    uint2 o;
    o.x = *(uint32_t*)&a;
    o.y = *(uint32_t*)&b;
    ((uint2*)g_wh)[i] = o;
}

// ---------------------------------------------------------------------------
// Kernel 1: GAT gather, bs-vectorized. One CTA per dst node, tid = bs index.
//   Edge list staged in smem, shared by all 256 bs columns; per edge one
//   coalesced 1KB load of x_t[s][:]. Direct expf per edge-lane (MUFU cheap).
// ---------------------------------------------------------------------------
__global__ __launch_bounds__(256) void gat_k(
    const float* __restrict__ w_lin, const float* __restrict__ att_src,
    const float* __restrict__ att_dst)
{
    __shared__ int   ss[256];
    __shared__ float s_cs, s_cd;

    const int n   = blockIdx.x;
    const int tid = threadIdx.x;

    if (tid < 32) {
        float w = w_lin[tid];
        float a = w * att_src[tid];
        float b = w * att_dst[tid];
#pragma unroll
        for (int d = 16; d > 0; d >>= 1) {
            a += __shfl_xor_sync(0xFFFFFFFFu, a, d);
            b += __shfl_xor_sync(0xFFFFFFFFu, b, d);
        }
        if (tid == 0) { s_cs = a; s_cd = b; }
    }
    __syncthreads();
    const float cs = s_cs, cd = s_cd;

    const float xd = g_xt[(size_t)n * BS_ + tid];
    const float cz = cd * xd;

    // self loop
    float z0 = fmaf(cs, xd, cz);
    z0 = (z0 > 0.f) ? z0 : 0.2f * z0;
    float w0  = __expf(z0);
    float den = w0, num = w0 * xd;

    const int off = g_off[n], end = g_off[n + 1];
    for (int base = off; base < end; base += 256) {
        const int cnt = min(256, end - base);
        __syncthreads();
        if (tid < cnt) ss[tid] = g_src[base + tid];
        __syncthreads();
#pragma unroll 4
        for (int p = 0; p < cnt; p++) {
            float xv = g_xt[(size_t)ss[p] * BS_ + tid];
            float za = fmaf(cs, xv, cz);
            za = (za > 0.f) ? za : 0.2f * za;
            float wa = __expf(za);
            den += wa;
            num = fmaf(wa, xv, num);
        }
    }
    g_aggt[(size_t)n * BS_ + tid] = __fdividef(num, den);
}

// ---------------------------------------------------------------------------
// Kernel 2: fp16 GEMM via mma.sync. B tiles cp.async'd from pre-converted
//   g_wh; A tiles generated on the fly from g_aggt (L2-resident, MLP-16).
//   grid (74, 2). CTA 256x128, warp 64x64, double-buffered smem (98.5 KB).
// ---------------------------------------------------------------------------
#define OFF_WL   0
#define OFF_GB   128
#define OFF_A0   256
#define OFF_A1   33024
#define OFF_B0   65792
#define OFF_B1   82176
#define SMEM_TOT 98560

__device__ __forceinline__ void gen_A(
    char* sm, uint32_t oA, const float* wl, const float* gb, int c, int tid)
{
#pragma unroll
    for (int i = 0; i < 16; i++) {
        int idx = tid + i * 256;
        int row = idx >> 4, c4 = idx & 15;
        float a  = __ldg(&g_aggt[(size_t)(c * 2 + (c4 >> 3)) * BS_ + row]);
        int   g0 = (c4 & 7) * 4;
        float v0 = fmaxf(fmaf(a, wl[g0],     gb[g0]),     0.f);
        float v1 = fmaxf(fmaf(a, wl[g0 + 1], gb[g0 + 1]), 0.f);
        float v2 = fmaxf(fmaf(a, wl[g0 + 2], gb[g0 + 2]), 0.f);
        float v3 = fmaxf(fmaf(a, wl[g0 + 3], gb[g0 + 3]), 0.f);
        __half2 h0 = __floats2half2_rn(v0, v1);
        __half2 h1 = __floats2half2_rn(v2, v3);
        uint2 o;
        o.x = *(uint32_t*)&h0;
        o.y = *(uint32_t*)&h1;
        *(uint2*)(sm + oA + SWZ((uint32_t)(row * 128 + c4 * 8))) = o;
    }
}

__device__ __forceinline__ void load_B(
    uint32_t sb, uint32_t oB, int nh, int c, int tid)
{
#pragma unroll
    for (int i = 0; i < 4; i++) {
        int idx = tid + i * 256;
        int row = idx >> 3, c8 = idx & 7;
        const __half* src = g_wh + (size_t)(nh * 128 + row) * D_ + c * 64 + c8 * 8;
        cp16(sb + oB + SWZ((uint32_t)(row * 128 + c8 * 16)), src);
    }
    CP_COMMIT();
}

__global__ __launch_bounds__(256) void gemm_k(
    const float* __restrict__ w_lin_g, const float* __restrict__ gbias_g)
{
    extern __shared__ __align__(128) char sm[];
    const uint32_t sb = smem_u32(sm);
    const int tid  = threadIdx.x;
    const int lane = tid & 31;
    const int wid  = tid >> 5;
    const int z    = blockIdx.x;           // K split
    const int nh   = blockIdx.y;           // gate half
    const int c0   = z * NCHUNK / KSPLIT;
    const int c1   = (z + 1) * NCHUNK / KSPLIT;

    if (tid < 32) {
        ((float*)(sm + OFF_WL))[tid] = w_lin_g[tid];
        ((float*)(sm + OFF_GB))[tid] = gbias_g[tid];
    }
    __syncthreads();

    const float* wl = (const float*)(sm + OFF_WL);
    const float* gb = (const float*)(sm + OFF_GB);

    const uint32_t AB[2] = {OFF_A0, OFF_A1};
    const uint32_t BB[2] = {OFF_B0, OFF_B1};

    const int mw = (wid & 3) * 64;
    const int nw = (wid >> 2) * 64;

    const uint32_t rowA = (uint32_t)(mw + (lane & 15)) * 128u;
    const uint32_t khA  = (uint32_t)(lane >> 4);
    const uint32_t swA  = (uint32_t)(lane & 7);
    const uint32_t rowB = (uint32_t)(nw + (lane & 7) + ((lane >> 4) << 3)) * 128u;
    const uint32_t khB  = (uint32_t)((lane >> 3) & 1);
    const uint32_t swB  = (uint32_t)(lane & 7);

    float acc[4][8][4];
#pragma unroll
    for (int mt = 0; mt < 4; mt++)
#pragma unroll
        for (int nt = 0; nt < 8; nt++)
#pragma unroll
            for (int q = 0; q < 4; q++) acc[mt][nt][q] = 0.f;

    // prologue: buffer 0
    load_B(sb, BB[0], nh, c0, tid);
    gen_A(sm, AB[0], wl, gb, c0, tid);
    CP_WAIT0();
    __syncthreads();

    for (int c = c0; c < c1; c++) {
        const int st = (c - c0) & 1;
        const int have_next = (c + 1 < c1);
        if (have_next) {
            load_B(sb, BB[st ^ 1], nh, c + 1, tid);     // async, in-flight
            gen_A(sm, AB[st ^ 1], wl, gb, c + 1, tid);  // overlaps cp.async
        }

        const uint32_t bA = sb + AB[st];
        const uint32_t bB = sb + BB[st];
#pragma unroll
        for (int ks = 0; ks < 4; ks++) {
            uint32_t af[4][4], bh[4][4];
            const uint32_t cA = (((uint32_t)(ks * 2) + khA) ^ swA) << 4;
            const uint32_t cB = (((uint32_t)(ks * 2) + khB) ^ swB) << 4;
#pragma unroll
            for (int np = 0; np < 4; np++)
                ldsm4(bh[np], bB + rowB + np * 2048 + cB);
#pragma unroll
            for (int mt = 0; mt < 4; mt++)
                ldsm4(af[mt], bA + rowA + mt * 2048 + cA);
#pragma unroll
            for (int mt = 0; mt < 4; mt++)
#pragma unroll
                for (int nt = 0; nt < 8; nt++)
                    mma16816(acc[mt][nt], af[mt], &bh[nt >> 1][(nt & 1) * 2]);
        }
        if (have_next) CP_WAIT0();
        __syncthreads();
    }

    const int gq = lane >> 2;
    const int t2 = (lane & 3) * 2;
    float* base = g_part + (size_t)z * (BS_ * G4_);
#pragma unroll
    for (int mt = 0; mt < 4; mt++)
#pragma unroll
        for (int nt = 0; nt < 8; nt++) {
            int row = mw + mt * 16 + gq;
            int col = nh * 128 + nw + nt * 8 + t2;
            *(float2*)(base + (size_t)row * G4_ + col) =
                make_float2(acc[mt][nt][0], acc[mt][nt][1]);
            *(float2*)(base + (size_t)(row + 8) * G4_ + col) =
                make_float2(acc[mt][nt][2], acc[mt][nt][3]);
        }
}

// ---------------------------------------------------------------------------
// Kernel 2b: reduce K-split partials into g_pg
// ---------------------------------------------------------------------------
__global__ __launch_bounds__(256) void reduce_k() {
    const int i = blockIdx.x * 256 + threadIdx.x;
    float s0 = 0.f, s1 = 0.f, s2 = 0.f, s3 = 0.f;
#pragma unroll
    for (int zz = 0; zz < 72; zz += 4) {
        s0 += g_part[(size_t)(zz + 0) * 65536 + i];
        s1 += g_part[(size_t)(zz + 1) * 65536 + i];
        s2 += g_part[(size_t)(zz + 2) * 65536 + i];
        s3 += g_part[(size_t)(zz + 3) * 65536 + i];
    }
    s0 += g_part[(size_t)72 * 65536 + i];
    s1 += g_part[(size_t)73 * 65536 + i];
    g_pg[i] = (s0 + s1) + (s2 + s3);
}

// ---------------------------------------------------------------------------
// Kernel 3: LSTM recurrence (pairs, W_hh in regs, 1 sync/step) + head GEMV
// ---------------------------------------------------------------------------
__global__ __launch_bounds__(128) void lstm_k(
    const float* __restrict__ W_hh, const float* __restrict__ b_ih,
    const float* __restrict__ b_hh, const float* __restrict__ W_head,
    const float* __restrict__ b_head, float* __restrict__ outp)
{
    __shared__ __align__(16) float hs[2][H_];

    const int t = threadIdx.x, b = blockIdx.x;
    const int j = t >> 1, p = t & 1;
    const int r0 = (p == 0) ? j          : H_ + j;      // i | f
    const int r1 = (p == 0) ? 2 * H_ + j : 3 * H_ + j;  // g | o

    float w0[H_], w1[H_];
#pragma unroll
    for (int k = 0; k < H_; k++) {
        w0[k] = W_hh[r0 * H_ + k];
        w1[k] = W_hh[r1 * H_ + k];
    }
    const float bias0 = b_ih[r0] + b_hh[r0];
    const float bias1 = b_ih[r1] + b_hh[r1];
    float cval = 0.f;
    if (p == 1) hs[0][j] = 0.f;
    float pg0 = g_pg[(b * S_) * G4_ + r0];
    float pg1 = g_pg[(b * S_) * G4_ + r1];
    __syncthreads();

    for (int s = 0; s < S_; s++) {
        float pn0 = 0.f, pn1 = 0.f;
        if (s + 1 < S_) {
            pn0 = g_pg[(b * S_ + s + 1) * G4_ + r0];
            pn1 = g_pg[(b * S_ + s + 1) * G4_ + r1];
        }
        const float4* h4 = (const float4*)(hs[s & 1]);
        float a0 = 0.f, a1 = 0.f, a2 = 0.f, a3 = 0.f;
        float d0 = 0.f, d1 = 0.f, d2 = 0.f, d3 = 0.f;
#pragma unroll
        for (int k = 0; k < 16; k++) {
            float4 hv = h4[k];
            a0 = fmaf(w0[4 * k],     hv.x, a0);
            a1 = fmaf(w0[4 * k + 1], hv.y, a1);
            a2 = fmaf(w0[4 * k + 2], hv.z, a2);
            a3 = fmaf(w0[4 * k + 3], hv.w, a3);
            d0 = fmaf(w1[4 * k],     hv.x, d0);
            d1 = fmaf(w1[4 * k + 1], hv.y, d1);
            d2 = fmaf(w1[4 * k + 2], hv.z, d2);
            d3 = fmaf(w1[4 * k + 3], hv.w, d3);
        }
        float g0 = (a0 + a1) + (a2 + a3) + pg0 + bias0;
        float g1 = (d0 + d1) + (d2 + d3) + pg1 + bias1;

        float s0 = sigm_f(g0);
        float s1 = (p == 0) ? tanh_f(g1) : sigm_f(g1);
        float prod  = s0 * s1;
        float other = __shfl_xor_sync(0xFFFFFFFFu, prod, 1);
        if (p == 1) {
            cval = fmaf(s0, cval, other);
            hs[(s + 1) & 1][j] = s1 * tanh_f(cval);
        }
        __syncthreads();
        pg0 = pn0;
        pg1 = pn1;
    }

    const float* hf = hs[S_ & 1];
    for (int n = t; n < N_; n += 128) {
        const float4* wr = (const float4*)(W_head + (size_t)n * H_);
        float acc = b_head[n];
#pragma unroll
        for (int q = 0; q < 16; q++) {
            float4 v = wr[q];
            acc = fmaf(v.x, hf[q * 4],     acc);
            acc = fmaf(v.y, hf[q * 4 + 1], acc);
            acc = fmaf(v.z, hf[q * 4 + 2], acc);
            acc = fmaf(v.w, hf[q * 4 + 3], acc);
        }
        outp[b * N_ + n] = acc;
    }
}

// ---------------------------------------------------------------------------
extern "C" void kernel_launch(void* const* d_in, const int* in_sizes, int n_in,
                              void* d_out, int out_size)
{
    const float* x       = (const float*)d_in[0];
    const int*   ei      = (const int*)  d_in[1];
    const float* w_lin   = (const float*)d_in[2];
    const float* att_src = (const float*)d_in[3];
    const float* att_dst = (const float*)d_in[4];
    const float* gbias   = (const float*)d_in[5];
    const float* W_ih    = (const float*)d_in[6];
    const float* W_hh    = (const float*)d_in[7];
    const float* b_ih    = (const float*)d_in[8];
    const float* b_hh    = (const float*)d_in[9];
    const float* W_head  = (const float*)d_in[10];
    const float* b_head  = (const float*)d_in[11];
    float*       out     = (float*)d_out;
    const int    E       = in_sizes[1] / 2;

    static int smem_set = 0;
    if (!smem_set) {
        cudaFuncSetAttribute(gemm_k, cudaFuncAttributeMaxDynamicSharedMemorySize,
                             SMEM_TOT);
        smem_set = 1;
    }

    wconv_k<<<(G4_ * (D_ / 4)) / 256, 256>>>(W_ih);            // W_ih -> fp16
    hist_k<<<(E + 255) / 256, 256>>>(ei, E);
    scan_k<<<1, 512>>>(E);
    scat_k<<<(E + 255) / 256, 256>>>(ei, E);
    xpose_k<<<dim3((N_ + 31) / 32, BS_ / 32), 256>>>(x);       // x -> x_t
    gat_k<<<N_, 256>>>(w_lin, att_src, att_dst);
    gemm_k<<<dim3(KSPLIT, NSPL), 256, SMEM_TOT>>>(w_lin, gbias);
    reduce_k<<<(BS_ * G4_) / 256, 256>>>();
    lstm_k<<<B_, 128>>>(W_hh, b_ih, b_hh, W_head, b_head, out);
}

// round 17
// speedup vs baseline: 4.1218x; 1.0667x over previous
#include <cuda_runtime.h>
#include <cuda_fp16.h>
#include <cstdint>

// ---------------------------------------------------------------------------
#define B_   8
#define S_   32
#define N_   2000
#define GH_  32
#define H_   64
#define D_   64000          // N_*GH_
#define BS_  256
#define G4_  256

#define KSPLIT 74           // K-splits (each 13-14 chunks of 64 over D_)
#define NSPL   2            // gate halves (128 each)
#define NCHUNK 1000         // D_/64

// prep_k role partition (CSR first => wave-1 residency for the spin barrier)
#define CSR_CTAS   250
#define XPOSE_NB   63                        // ceil(N_/32)
#define XPOSE_CTAS (XPOSE_NB * (BS_ / 32))   // 504
#define WCONV_CTAS ((G4_ * (D_ / 4)) / 256)  // 16384
#define PREP_CTAS  (CSR_CTAS + XPOSE_CTAS + WCONV_CTAS)

__device__ float  g_xt[N_ * BS_];                    // 2 MB   x transposed [n][bs]
__device__ float  g_aggt[N_ * BS_];                  // 2 MB   agg [n][bs]
__device__ float  g_pg[BS_ * G4_];                   // 256 KB pre-gates
__device__ float  g_part[KSPLIT * BS_ * G4_];        // 19.4 MB GEMM partials
__device__ __half g_wh[(size_t)G4_ * D_];            // 32 MB  W_ih in fp16
// CSR scratch + single-pass coordination (all left zeroed for next replay)
__device__ int    g_cnt[N_];
__device__ int    g_off[N_ + 1];
__device__ int    g_cur[N_];
__device__ int    g_src[131072];
__device__ int    g_done  = 0;
__device__ int    g_done2 = 0;
__device__ int    g_flag  = 0;

// ---------------------------------------------------------------------------
// helpers
// ---------------------------------------------------------------------------
__device__ __forceinline__ uint32_t smem_u32(const void* p) {
    uint32_t a;
    asm("{ .reg .u64 t; cvta.to.shared.u64 t, %1; cvt.u32.u64 %0, t; }"
        : "=r"(a) : "l"(p));
    return a;
}
#define SWZ(o) ((o) ^ (((o) >> 3) & 0x70))

__device__ __forceinline__ void ldsm4(uint32_t* r, uint32_t addr) {
    asm volatile("ldmatrix.sync.aligned.m8n8.x4.shared.b16 {%0,%1,%2,%3}, [%4];"
                 : "=r"(r[0]), "=r"(r[1]), "=r"(r[2]), "=r"(r[3]) : "r"(addr));
}
__device__ __forceinline__ void mma16816(float* c, const uint32_t* a,
                                         const uint32_t* b) {
    asm volatile(
        "mma.sync.aligned.m16n8k16.row.col.f32.f16.f16.f32 "
        "{%0,%1,%2,%3}, {%4,%5,%6,%7}, {%8,%9}, {%0,%1,%2,%3};"
        : "+f"(c[0]), "+f"(c[1]), "+f"(c[2]), "+f"(c[3])
        : "r"(a[0]), "r"(a[1]), "r"(a[2]), "r"(a[3]), "r"(b[0]), "r"(b[1]));
}
__device__ __forceinline__ void cp16(uint32_t dst, const void* src) {
    asm volatile("cp.async.cg.shared.global [%0], [%1], 16;"
                 :: "r"(dst), "l"(src));
}
#define CP_COMMIT() asm volatile("cp.async.commit_group;" ::: "memory")
#define CP_WAIT0()  asm volatile("cp.async.wait_group 0;"  ::: "memory")

__device__ __forceinline__ float sigm_f(float v) {
    return __fdividef(1.f, 1.f + __expf(-v));
}
__device__ __forceinline__ float tanh_f(float v) {
    return 1.f - __fdividef(2.f, __expf(2.f * v) + 1.f);
}

// ---------------------------------------------------------------------------
// Kernel 0 (prep megakernel): CSR single-pass + x transpose + W_ih->fp16.
//   Role by blockIdx range. CSR CTAs (0..249) are all resident in wave 1,
//   so the flag spin cannot deadlock.
// ---------------------------------------------------------------------------
__global__ __launch_bounds__(256) void prep_k(
    const float* __restrict__ x, const float* __restrict__ W,
    const int* __restrict__ ei, int E)
{
    __shared__ int   wsum[8];
    __shared__ int   lastflag;
    __shared__ float tt[32][33];

    const int bid = blockIdx.x;
    const int tid = threadIdx.x;

    if (bid < CSR_CTAS) {
        // ---- phase 1: histogram of dst ----
        for (int t = bid * 256 + tid; t < E; t += CSR_CTAS * 256)
            atomicAdd(&g_cnt[ei[E + t]], 1);
        __threadfence();
        if (tid == 0) {
            int v = atomicAdd(&g_done, 1);
            lastflag = (v == CSR_CTAS - 1);
        }
        __syncthreads();

        if (lastflag) {
            // ---- phase 2 (last CTA only): exclusive scan of 2000 counts ----
            const int lane = tid & 31, wid = tid >> 5;
            const int base = tid * 8;
            int v[8], s = 0;
#pragma unroll
            for (int j = 0; j < 8; j++) {
                int idx = base + j;
                int c = (idx < N_) ? g_cnt[idx] : 0;
                if (idx < N_) g_cnt[idx] = 0;      // re-zero for next replay
                v[j] = c;
                s += c;
            }
            int ps = s;
#pragma unroll
            for (int d = 1; d < 32; d <<= 1) {
                int o = __shfl_up_sync(0xFFFFFFFFu, ps, d);
                if (lane >= d) ps += o;
            }
            if (lane == 31) wsum[wid] = ps;
            __syncthreads();
            if (tid < 8) {
                int w = wsum[tid];
#pragma unroll
                for (int d = 1; d < 8; d <<= 1) {
                    int o = __shfl_up_sync(0x000000FFu, w, d);
                    if (tid >= d) w += o;
                }
                wsum[tid] = w;
            }
            __syncthreads();
            int run = ((wid > 0) ? wsum[wid - 1] : 0) + ps - s;
#pragma unroll
            for (int j = 0; j < 8; j++) {
                int idx = base + j;
                if (idx < N_) {
                    g_off[idx] = run;
                    g_cur[idx] = run;
                    run += v[j];
                }
            }
            if (tid == 0) g_off[N_] = E;
            __threadfence();
            __syncthreads();
            if (tid == 0) atomicExch(&g_flag, 1);
        } else {
            // ---- spin until scan published (all CSR CTAs co-resident) ----
            if (tid == 0)
                while (atomicAdd(&g_flag, 0) == 0) __nanosleep(64);
            __syncthreads();
            __threadfence();
        }

        // ---- phase 3: scatter src into dst-sorted order ----
        for (int t = bid * 256 + tid; t < E; t += CSR_CTAS * 256) {
            int d = ei[E + t];
            int pos = atomicAdd(&g_cur[d], 1);
            g_src[pos] = ei[t];
        }
        // ---- cleanup coordination state for next replay ----
        __threadfence();
        if (tid == 0) {
            int v = atomicAdd(&g_done2, 1);
            if (v == CSR_CTAS - 1) {
                g_done = 0;
                g_done2 = 0;
                g_flag = 0;
            }
        }
    } else if (bid < CSR_CTAS + XPOSE_CTAS) {
        // ---- x [BS][N] -> g_xt [N][BS], 32x32 tiles ----
        const int b2 = bid - CSR_CTAS;
        const int nb = (b2 % XPOSE_NB) * 32, bb = (b2 / XPOSE_NB) * 32;
        const int tx = tid & 31, ty = tid >> 5;
#pragma unroll
        for (int j = 0; j < 32; j += 8) {
            int col = nb + tx;
            if (col < N_) tt[ty + j][tx] = x[(size_t)(bb + ty + j) * N_ + col];
        }
        __syncthreads();
#pragma unroll
        for (int j = 0; j < 32; j += 8) {
            int row = nb + ty + j;
            if (row < N_) g_xt[(size_t)row * BS_ + bb + tx] = tt[tx][ty + j];
        }
    } else {
        // ---- W_ih fp32 -> fp16 ----
        size_t i = (size_t)(bid - CSR_CTAS - XPOSE_CTAS) * 256 + tid;
        float4 w = ((const float4*)W)[i];
        __half2 a = __floats2half2_rn(w.x, w.y);
        __half2 b = __floats2half2_rn(w.z, w.w);
        uint2 o;
        o.x = *(uint32_t*)&a;
        o.y = *(uint32_t*)&b;
        ((uint2*)g_wh)[i] = o;
    }
}

// ---------------------------------------------------------------------------
// Kernel 1: GAT gather, bs-vectorized. One CTA per dst node, tid = bs index.
// ---------------------------------------------------------------------------
__global__ __launch_bounds__(256) void gat_k(
    const float* __restrict__ w_lin, const float* __restrict__ att_src,
    const float* __restrict__ att_dst)
{
    __shared__ int   ss[256];
    __shared__ float s_cs, s_cd;

    const int n   = blockIdx.x;
    const int tid = threadIdx.x;

    if (tid < 32) {
        float w = w_lin[tid];
        float a = w * att_src[tid];
        float b = w * att_dst[tid];
#pragma unroll
        for (int d = 16; d > 0; d >>= 1) {
            a += __shfl_xor_sync(0xFFFFFFFFu, a, d);
            b += __shfl_xor_sync(0xFFFFFFFFu, b, d);
        }
        if (tid == 0) { s_cs = a; s_cd = b; }
    }
    __syncthreads();
    const float cs = s_cs, cd = s_cd;

    const float xd = g_xt[(size_t)n * BS_ + tid];
    const float cz = cd * xd;

    float z0 = fmaf(cs, xd, cz);
    z0 = (z0 > 0.f) ? z0 : 0.2f * z0;
    float w0  = __expf(z0);
    float den = w0, num = w0 * xd;

    const int off = g_off[n], end = g_off[n + 1];
    for (int base = off; base < end; base += 256) {
        const int cnt = min(256, end - base);
        __syncthreads();
        if (tid < cnt) ss[tid] = g_src[base + tid];
        __syncthreads();
#pragma unroll 4
        for (int p = 0; p < cnt; p++) {
            float xv = g_xt[(size_t)ss[p] * BS_ + tid];
            float za = fmaf(cs, xv, cz);
            za = (za > 0.f) ? za : 0.2f * za;
            float wa = __expf(za);
            den += wa;
            num = fmaf(wa, xv, num);
        }
    }
    g_aggt[(size_t)n * BS_ + tid] = __fdividef(num, den);
}

// ---------------------------------------------------------------------------
// Kernel 2: fp16 GEMM via mma.sync; B via cp.async from g_wh, A generated
//   on the fly from g_aggt. grid (74,2). CTA 256x128, warp 64x64, 2-stage.
// ---------------------------------------------------------------------------
#define OFF_WL   0
#define OFF_GB   128
#define OFF_A0   256
#define OFF_A1   33024
#define OFF_B0   65792
#define OFF_B1   82176
#define SMEM_TOT 98560

__device__ __forceinline__ void gen_A(
    char* sm, uint32_t oA, const float* wl, const float* gb, int c, int tid)
{
#pragma unroll
    for (int i = 0; i < 16; i++) {
        int idx = tid + i * 256;
        int row = idx >> 4, c4 = idx & 15;
        float a  = __ldg(&g_aggt[(size_t)(c * 2 + (c4 >> 3)) * BS_ + row]);
        int   g0 = (c4 & 7) * 4;
        float v0 = fmaxf(fmaf(a, wl[g0],     gb[g0]),     0.f);
        float v1 = fmaxf(fmaf(a, wl[g0 + 1], gb[g0 + 1]), 0.f);
        float v2 = fmaxf(fmaf(a, wl[g0 + 2], gb[g0 + 2]), 0.f);
        float v3 = fmaxf(fmaf(a, wl[g0 + 3], gb[g0 + 3]), 0.f);
        __half2 h0 = __floats2half2_rn(v0, v1);
        __half2 h1 = __floats2half2_rn(v2, v3);
        uint2 o;
        o.x = *(uint32_t*)&h0;
        o.y = *(uint32_t*)&h1;
        *(uint2*)(sm + oA + SWZ((uint32_t)(row * 128 + c4 * 8))) = o;
    }
}

__device__ __forceinline__ void load_B(
    uint32_t sb, uint32_t oB, int nh, int c, int tid)
{
#pragma unroll
    for (int i = 0; i < 4; i++) {
        int idx = tid + i * 256;
        int row = idx >> 3, c8 = idx & 7;
        const __half* src = g_wh + (size_t)(nh * 128 + row) * D_ + c * 64 + c8 * 8;
        cp16(sb + oB + SWZ((uint32_t)(row * 128 + c8 * 16)), src);
    }
    CP_COMMIT();
}

__global__ __launch_bounds__(256) void gemm_k(
    const float* __restrict__ w_lin_g, const float* __restrict__ gbias_g)
{
    extern __shared__ __align__(128) char sm[];
    const uint32_t sb = smem_u32(sm);
    const int tid  = threadIdx.x;
    const int lane = tid & 31;
    const int wid  = tid >> 5;
    const int z    = blockIdx.x;           // K split
    const int nh   = blockIdx.y;           // gate half
    const int c0   = z * NCHUNK / KSPLIT;
    const int c1   = (z + 1) * NCHUNK / KSPLIT;

    if (tid < 32) {
        ((float*)(sm + OFF_WL))[tid] = w_lin_g[tid];
        ((float*)(sm + OFF_GB))[tid] = gbias_g[tid];
    }
    __syncthreads();

    const float* wl = (const float*)(sm + OFF_WL);
    const float* gb = (const float*)(sm + OFF_GB);

    const uint32_t AB[2] = {OFF_A0, OFF_A1};
    const uint32_t BB[2] = {OFF_B0, OFF_B1};

    const int mw = (wid & 3) * 64;
    const int nw = (wid >> 2) * 64;

    const uint32_t rowA = (uint32_t)(mw + (lane & 15)) * 128u;
    const uint32_t khA  = (uint32_t)(lane >> 4);
    const uint32_t swA  = (uint32_t)(lane & 7);
    const uint32_t rowB = (uint32_t)(nw + (lane & 7) + ((lane >> 4) << 3)) * 128u;
    const uint32_t khB  = (uint32_t)((lane >> 3) & 1);
    const uint32_t swB  = (uint32_t)(lane & 7);

    float acc[4][8][4];
#pragma unroll
    for (int mt = 0; mt < 4; mt++)
#pragma unroll
        for (int nt = 0; nt < 8; nt++)
#pragma unroll
            for (int q = 0; q < 4; q++) acc[mt][nt][q] = 0.f;

    load_B(sb, BB[0], nh, c0, tid);
    gen_A(sm, AB[0], wl, gb, c0, tid);
    CP_WAIT0();
    __syncthreads();

    for (int c = c0; c < c1; c++) {
        const int st = (c - c0) & 1;
        const int have_next = (c + 1 < c1);
        if (have_next) {
            load_B(sb, BB[st ^ 1], nh, c + 1, tid);
            gen_A(sm, AB[st ^ 1], wl, gb, c + 1, tid);
        }

        const uint32_t bA = sb + AB[st];
        const uint32_t bB = sb + BB[st];
#pragma unroll
        for (int ks = 0; ks < 4; ks++) {
            uint32_t af[4][4], bh[4][4];
            const uint32_t cA = (((uint32_t)(ks * 2) + khA) ^ swA) << 4;
            const uint32_t cB = (((uint32_t)(ks * 2) + khB) ^ swB) << 4;
#pragma unroll
            for (int np = 0; np < 4; np++)
                ldsm4(bh[np], bB + rowB + np * 2048 + cB);
#pragma unroll
            for (int mt = 0; mt < 4; mt++)
                ldsm4(af[mt], bA + rowA + mt * 2048 + cA);
#pragma unroll
            for (int mt = 0; mt < 4; mt++)
#pragma unroll
                for (int nt = 0; nt < 8; nt++)
                    mma16816(acc[mt][nt], af[mt], &bh[nt >> 1][(nt & 1) * 2]);
        }
        if (have_next) CP_WAIT0();
        __syncthreads();
    }

    const int gq = lane >> 2;
    const int t2 = (lane & 3) * 2;
    float* base = g_part + (size_t)z * (BS_ * G4_);
#pragma unroll
    for (int mt = 0; mt < 4; mt++)
#pragma unroll
        for (int nt = 0; nt < 8; nt++) {
            int row = mw + mt * 16 + gq;
            int col = nh * 128 + nw + nt * 8 + t2;
            *(float2*)(base + (size_t)row * G4_ + col) =
                make_float2(acc[mt][nt][0], acc[mt][nt][1]);
            *(float2*)(base + (size_t)(row + 8) * G4_ + col) =
                make_float2(acc[mt][nt][2], acc[mt][nt][3]);
        }
}

// ---------------------------------------------------------------------------
// Kernel 2b: reduce K-split partials into g_pg
// ---------------------------------------------------------------------------
__global__ __launch_bounds__(256) void reduce_k() {
    const int i = blockIdx.x * 256 + threadIdx.x;
    float s0 = 0.f, s1 = 0.f, s2 = 0.f, s3 = 0.f;
#pragma unroll
    for (int zz = 0; zz < 72; zz += 4) {
        s0 += g_part[(size_t)(zz + 0) * 65536 + i];
        s1 += g_part[(size_t)(zz + 1) * 65536 + i];
        s2 += g_part[(size_t)(zz + 2) * 65536 + i];
        s3 += g_part[(size_t)(zz + 3) * 65536 + i];
    }
    s0 += g_part[(size_t)72 * 65536 + i];
    s1 += g_part[(size_t)73 * 65536 + i];
    g_pg[i] = (s0 + s1) + (s2 + s3);
}

// ---------------------------------------------------------------------------
// Kernel 3: LSTM recurrence (pairs, W_hh in regs, 1 sync/step) + head GEMV
// ---------------------------------------------------------------------------
__global__ __launch_bounds__(128) void lstm_k(
    const float* __restrict__ W_hh, const float* __restrict__ b_ih,
    const float* __restrict__ b_hh, const float* __restrict__ W_head,
    const float* __restrict__ b_head, float* __restrict__ outp)
{
    __shared__ __align__(16) float hs[2][H_];

    const int t = threadIdx.x, b = blockIdx.x;
    const int j = t >> 1, p = t & 1;
    const int r0 = (p == 0) ? j          : H_ + j;      // i | f
    const int r1 = (p == 0) ? 2 * H_ + j : 3 * H_ + j;  // g | o

    float w0[H_], w1[H_];
#pragma unroll
    for (int k = 0; k < H_; k++) {
        w0[k] = W_hh[r0 * H_ + k];
        w1[k] = W_hh[r1 * H_ + k];
    }
    const float bias0 = b_ih[r0] + b_hh[r0];
    const float bias1 = b_ih[r1] + b_hh[r1];
    float cval = 0.f;
    if (p == 1) hs[0][j] = 0.f;
    float pg0 = g_pg[(b * S_) * G4_ + r0];
    float pg1 = g_pg[(b * S_) * G4_ + r1];
    __syncthreads();

    for (int s = 0; s < S_; s++) {
        float pn0 = 0.f, pn1 = 0.f;
        if (s + 1 < S_) {
            pn0 = g_pg[(b * S_ + s + 1) * G4_ + r0];
            pn1 = g_pg[(b * S_ + s + 1) * G4_ + r1];
        }
        const float4* h4 = (const float4*)(hs[s & 1]);
        float a0 = 0.f, a1 = 0.f, a2 = 0.f, a3 = 0.f;
        float d0 = 0.f, d1 = 0.f, d2 = 0.f, d3 = 0.f;
#pragma unroll
        for (int k = 0; k < 16; k++) {
            float4 hv = h4[k];
            a0 = fmaf(w0[4 * k],     hv.x, a0);
            a1 = fmaf(w0[4 * k + 1], hv.y, a1);
            a2 = fmaf(w0[4 * k + 2], hv.z, a2);
            a3 = fmaf(w0[4 * k + 3], hv.w, a3);
            d0 = fmaf(w1[4 * k],     hv.x, d0);
            d1 = fmaf(w1[4 * k + 1], hv.y, d1);
            d2 = fmaf(w1[4 * k + 2], hv.z, d2);
            d3 = fmaf(w1[4 * k + 3], hv.w, d3);
        }
        float g0 = (a0 + a1) + (a2 + a3) + pg0 + bias0;
        float g1 = (d0 + d1) + (d2 + d3) + pg1 + bias1;

        float s0 = sigm_f(g0);
        float s1 = (p == 0) ? tanh_f(g1) : sigm_f(g1);
        float prod  = s0 * s1;
        float other = __shfl_xor_sync(0xFFFFFFFFu, prod, 1);
        if (p == 1) {
            cval = fmaf(s0, cval, other);
            hs[(s + 1) & 1][j] = s1 * tanh_f(cval);
        }
        __syncthreads();
        pg0 = pn0;
        pg1 = pn1;
    }

    const float* hf = hs[S_ & 1];
    for (int n = t; n < N_; n += 128) {
        const float4* wr = (const float4*)(W_head + (size_t)n * H_);
        float acc = b_head[n];
#pragma unroll
        for (int q = 0; q < 16; q++) {
            float4 v = wr[q];
            acc = fmaf(v.x, hf[q * 4],     acc);
            acc = fmaf(v.y, hf[q * 4 + 1], acc);
            acc = fmaf(v.z, hf[q * 4 + 2], acc);
            acc = fmaf(v.w, hf[q * 4 + 3], acc);
        }
        outp[b * N_ + n] = acc;
    }
}

// ---------------------------------------------------------------------------
extern "C" void kernel_launch(void* const* d_in, const int* in_sizes, int n_in,
                              void* d_out, int out_size)
{
    const float* x       = (const float*)d_in[0];
    const int*   ei      = (const int*)  d_in[1];
    const float* w_lin   = (const float*)d_in[2];
    const float* att_src = (const float*)d_in[3];
    const float* att_dst = (const float*)d_in[4];
    const float* gbias   = (const float*)d_in[5];
    const float* W_ih    = (const float*)d_in[6];
    const float* W_hh    = (const float*)d_in[7];
    const float* b_ih    = (const float*)d_in[8];
    const float* b_hh    = (const float*)d_in[9];
    const float* W_head  = (const float*)d_in[10];
    const float* b_head  = (const float*)d_in[11];
    float*       out     = (float*)d_out;
    const int    E       = in_sizes[1] / 2;

    static int smem_set = 0;
    if (!smem_set) {
        cudaFuncSetAttribute(gemm_k, cudaFuncAttributeMaxDynamicSharedMemorySize,
                             SMEM_TOT);
        smem_set = 1;
    }

    prep_k<<<PREP_CTAS, 256>>>(x, W_ih, ei, E);                 // CSR+xpose+wconv
    gat_k<<<N_, 256>>>(w_lin, att_src, att_dst);
    gemm_k<<<dim3(KSPLIT, NSPL), 256, SMEM_TOT>>>(w_lin, gbias);
    reduce_k<<<(BS_ * G4_) / 256, 256>>>();
    lstm_k<<<B_, 128>>>(W_hh, b_ih, b_hh, W_head, b_head, out);
}